// round 9
// baseline (speedup 1.0000x reference)
#include <cuda_runtime.h>
#include <cuda_bf16.h>
#include <cuda_fp16.h>
#include <cstdint>

#define BATCH 8
#define NN 2048
#define EE 2048

#define BM 128
#define BN 128
#define STAGE_BYTES 32768       // A: 128x128B (16KB) + B: 128x128B (16KB)
#define NSTG 3

// ---------------- scratch globals (no cudaMalloc allowed) ----------------
__device__ __align__(256) __nv_bfloat16 g_xh[(size_t)BATCH * NN * EE];
__device__ __align__(256) __nv_bfloat16 g_xl[(size_t)BATCH * NN * EE];
__device__ __align__(256) __half        g_xf[(size_t)BATCH * NN * EE];
__device__ __align__(256) __nv_bfloat16 g_wh[(size_t)EE * EE];
__device__ __align__(256) __nv_bfloat16 g_wl[(size_t)EE * EE];
__device__ __align__(256) __nv_bfloat16 g_qh[(size_t)BATCH * NN * EE];
__device__ __align__(256) __nv_bfloat16 g_ql[(size_t)BATCH * NN * EE];
__device__ __align__(256) __half        g_af[(size_t)BATCH * NN * NN];
__device__ __align__(256) float         g_s [(size_t)BATCH * NN * NN];
__device__ __align__(256) float         g_cmax[BATCH * NN];
__device__ __align__(256) float         g_csum[BATCH * NN];

// ---------------- helpers ----------------
__device__ __forceinline__ uint32_t smem_u32(const void* p) {
    uint32_t a;
    asm("{ .reg .u64 t; cvta.to.shared.u64 t, %1; cvt.u32.u64 %0, t; }" : "=r"(a) : "l"(p));
    return a;
}
__device__ __forceinline__ void cp16(uint32_t s, const void* g) {
    asm volatile("cp.async.cg.shared.global [%0], [%1], 16;" :: "r"(s), "l"(g) : "memory");
}
__device__ __forceinline__ void cp_commit() {
    asm volatile("cp.async.commit_group;" ::: "memory");
}
template <int N> __device__ __forceinline__ void cp_wait() {
    asm volatile("cp.async.wait_group %0;" :: "n"(N) : "memory");
}
__device__ __forceinline__ void ldm4(uint32_t* r, uint32_t a) {
    asm volatile("ldmatrix.sync.aligned.m8n8.x4.shared.b16 {%0,%1,%2,%3}, [%4];"
                 : "=r"(r[0]), "=r"(r[1]), "=r"(r[2]), "=r"(r[3]) : "r"(a));
}
template <bool F16>
__device__ __forceinline__ void mma16816(float* c, const uint32_t* a, uint32_t b0, uint32_t b1) {
    if (F16)
        asm volatile(
            "mma.sync.aligned.m16n8k16.row.col.f32.f16.f16.f32 "
            "{%0,%1,%2,%3}, {%4,%5,%6,%7}, {%8,%9}, {%0,%1,%2,%3};"
            : "+f"(c[0]), "+f"(c[1]), "+f"(c[2]), "+f"(c[3])
            : "r"(a[0]), "r"(a[1]), "r"(a[2]), "r"(a[3]), "r"(b0), "r"(b1));
    else
        asm volatile(
            "mma.sync.aligned.m16n8k16.row.col.f32.bf16.bf16.f32 "
            "{%0,%1,%2,%3}, {%4,%5,%6,%7}, {%8,%9}, {%0,%1,%2,%3};"
            : "+f"(c[0]), "+f"(c[1]), "+f"(c[2]), "+f"(c[3])
            : "r"(a[0]), "r"(a[1]), "r"(a[2]), "r"(a[3]), "r"(b0), "r"(b1));
}

// ---------------- persistent tensor-core GEMM: C tiles 128x128 = A @ B^T ----------------
// 128-thread CTAs, 2 CTAs/SM (96KB smem each) so SMSP warp pairs come from
// DIFFERENT CTAs -> desynchronized barriers cover each other's stalls.
// Phases over K' = nbk*64: kbn>>5 selects (Ah,Bh) / (Al,Bh) / (Ah,Bl).
// nbk=96: 3-phase split.  nbk=32: single-phase.
// mode 0: fp32 to outF. mode 1: split-store hi/lo bf16 to outH/outL.
template <bool F16>
__global__ __launch_bounds__(128, 2)
void gemm_mma(const void* Ahv, const void* Alv, const void* Bhv, const void* Blv,
              long long aBatch, long long bBatch, long long cBatch,
              float* outF, __nv_bfloat16* outH, __nv_bfloat16* outL, int mode,
              int gx, int gy, int nTiles, int nbk)
{
    extern __shared__ __align__(128) char smem[];
    const uint32_t stg0 = smem_u32(smem);
    const int tid  = threadIdx.x;
    const int lane = tid & 31;
    const int warp = tid >> 5;                  // 0..3

    // -------- producer mapping: 128 threads, 16 rows per pass, 8 passes each for A/B ----
    const int lr = tid >> 3;                    // 0..15
    const int lc = tid & 7;                     // 16B chunk in 128B row
    const uint32_t so = (uint32_t)(lr * 128 + ((lc ^ (lr & 7)) << 4));

    // -------- mma fragment addressing (warp tile 64x64, 2x2 warp layout) --------
    const int wm  = warp & 1;
    const int wn  = warp >> 1;
    const int m0w = wm * 64;
    const int n0w = wn * 64;
    const uint32_t aRow  = (uint32_t)(m0w + (lane & 15));
    const uint32_t aBase = aRow * 128;
    const uint32_t aXor  = aRow & 7;
    const uint32_t ac0   = (uint32_t)(lane >> 4);
    const uint32_t bRow  = (uint32_t)(n0w + ((lane >> 4) << 3) + (lane & 7));
    const uint32_t bBase = 16384u + bRow * 128;
    const uint32_t bXor  = (uint32_t)(lane & 7);
    const uint32_t bc0   = (uint32_t)((lane >> 3) & 1);

    float acc[4][8][4] = {};
    uint32_t af[2][4][4], bf[2][4][4];          // double-buffered fragments

    const char *gAh, *gAl, *gBh, *gBl;
    auto setLoad = [&](int tt) {
        const int bx = tt % gx;
        const int r2 = tt / gx;
        const int by = r2 % gy;
        const int bz = r2 / gy;
        const size_t aoff = ((size_t)bz * (size_t)aBatch + (size_t)(by * BM + lr) * EE) * 2 + lc * 16;
        const size_t boff = ((size_t)bz * (size_t)bBatch + (size_t)(bx * BN + lr) * EE) * 2 + lc * 16;
        gAh = (const char*)Ahv + aoff;
        gAl = (const char*)Alv + aoff;
        gBh = (const char*)Bhv + boff;
        gBl = (const char*)Blv + boff;
    };

    // full stage load: 16 cp16 per thread, one commit group
    auto load_stage = [&](int slot, int kbn) {
        const int p = kbn >> 5;
        const char* a = (p == 1) ? gAl : gAh;
        const char* b = (p == 2) ? gBl : gBh;
        const uint32_t koff = (uint32_t)(kbn & 31) * 128;
        const uint32_t dstA = stg0 + (uint32_t)slot * STAGE_BYTES + so;
        const uint32_t dstB = dstA + 16384u;
#pragma unroll
        for (int i = 0; i < 8; i++)
            cp16(dstA + (uint32_t)i * 2048u, a + koff + (size_t)i * 65536);
#pragma unroll
        for (int i = 0; i < 8; i++)
            cp16(dstB + (uint32_t)i * 2048u, b + koff + (size_t)i * 65536);
        cp_commit();
    };
    auto ldm_ks = [&](uint32_t sb_, uint32_t ke, int bsel) {
#pragma unroll
        for (int mt = 0; mt < 4; mt++)
            ldm4(af[bsel][mt], sb_ + aBase + mt * 2048u + (((ke * 2 + ac0) ^ aXor) << 4));
#pragma unroll
        for (int np = 0; np < 4; np++)
            ldm4(bf[bsel][np], sb_ + bBase + np * 2048u + (((ke * 2 + bc0) ^ bXor) << 4));
    };

    int t = blockIdx.x;
    if (t >= nTiles) return;
    setLoad(t);
    load_stage(0, 0);
    load_stage(1, 1);
    load_stage(2, 2);
    cp_wait<1>();                 // stages 0,1 complete
    __syncthreads();
    ldm_ks(stg0, 0, 0);           // kb=0 ks=0 fragments

    int slot = 0;                 // global stage slot, continuous across tiles
    for (;;) {
        const int bx = t % gx;
        const int r2 = t / gx;
        const int row0 = (r2 % gy) * BM;
        const int col0 = bx * BN;
        const int z    = r2 / gy;
        const bool hasNext = (t + (int)gridDim.x) < nTiles;

        for (int kb = 0; kb < nbk; kb++) {
            const uint32_t sb = stg0 + (uint32_t)slot * STAGE_BYTES;
            const int nextSlot = (slot == NSTG - 1) ? 0 : slot + 1;
#pragma unroll
            for (int ks = 0; ks < 4; ks++) {
                const int cur = ks & 1;
                if (ks < 3)
                    ldm_ks(sb, (uint32_t)ks + 1, cur ^ 1);
                else if (kb + 1 < nbk || hasNext)
                    ldm_ks(stg0 + (uint32_t)nextSlot * STAGE_BYTES, 0, cur ^ 1);
#pragma unroll
                for (int mt = 0; mt < 4; mt++)
#pragma unroll
                    for (int np = 0; np < 4; np++) {
                        mma16816<F16>(acc[mt][np * 2],     af[cur][mt], bf[cur][np][0], bf[cur][np][1]);
                        mma16816<F16>(acc[mt][np * 2 + 1], af[cur][mt], bf[cur][np][2], bf[cur][np][3]);
                    }
            }
            __syncthreads();                       // all reads of this slot done
            const bool doLoad = (kb + 3 < nbk) || hasNext;
            if (kb == nbk - 3 && hasNext) setLoad(t + (int)gridDim.x);
            if (doLoad) {
                const int kbn = (kb + 3 < nbk) ? kb + 3 : kb + 3 - nbk;
                load_stage(slot, kbn);             // (kb+3) % 3 == kb % 3
            }
            if (kb + 1 < nbk) {
                if (!hasNext && kb + 1 >= nbk - 2) cp_wait<0>(); else cp_wait<1>();
                __syncthreads();
            }
            slot = nextSlot;
        }

        // -------- epilogue (next tile's stage loads in flight) --------
        const int g  = lane >> 2;
        const int tg = lane & 3;
        if (mode == 0) {
            float* base = outF + (size_t)z * (size_t)cBatch;
#pragma unroll
            for (int mt = 0; mt < 4; mt++) {
                const int rg = row0 + m0w + mt * 16 + g;
#pragma unroll
                for (int nt = 0; nt < 8; nt++) {
                    const int cg = col0 + n0w + nt * 8 + 2 * tg;
                    *(float2*)(base + (size_t)rg * 2048 + cg)       = make_float2(acc[mt][nt][0], acc[mt][nt][1]);
                    *(float2*)(base + (size_t)(rg + 8) * 2048 + cg) = make_float2(acc[mt][nt][2], acc[mt][nt][3]);
                }
            }
        } else {
#pragma unroll
            for (int mt = 0; mt < 4; mt++) {
                const int rg = row0 + m0w + mt * 16 + g;
#pragma unroll
                for (int nt = 0; nt < 8; nt++) {
                    const int cg = col0 + n0w + nt * 8 + 2 * tg;
                    float v[4] = {acc[mt][nt][0], acc[mt][nt][1], acc[mt][nt][2], acc[mt][nt][3]};
                    __nv_bfloat16 h0 = __float2bfloat16(v[0]), h1 = __float2bfloat16(v[1]);
                    __nv_bfloat16 h2 = __float2bfloat16(v[2]), h3 = __float2bfloat16(v[3]);
                    __nv_bfloat16 l0 = __float2bfloat16(v[0] - __bfloat162float(h0));
                    __nv_bfloat16 l1 = __float2bfloat16(v[1] - __bfloat162float(h1));
                    __nv_bfloat16 l2 = __float2bfloat16(v[2] - __bfloat162float(h2));
                    __nv_bfloat16 l3 = __float2bfloat16(v[3] - __bfloat162float(h3));
                    *(__nv_bfloat162*)(outH + (size_t)rg * 2048 + cg)       = __nv_bfloat162(h0, h1);
                    *(__nv_bfloat162*)(outL + (size_t)rg * 2048 + cg)       = __nv_bfloat162(l0, l1);
                    *(__nv_bfloat162*)(outH + (size_t)(rg + 8) * 2048 + cg) = __nv_bfloat162(h2, h3);
                    *(__nv_bfloat162*)(outL + (size_t)(rg + 8) * 2048 + cg) = __nv_bfloat162(l2, l3);
                }
            }
        }
        if (!hasNext) break;
#pragma unroll
        for (int mt = 0; mt < 4; mt++)
#pragma unroll
            for (int nt = 0; nt < 8; nt++)
#pragma unroll
                for (int q = 0; q < 4; q++) acc[mt][nt][q] = 0.0f;
        t += (int)gridDim.x;
        cp_wait<1>();            // next tile stages 0,1 ready
        __syncthreads();
    }
}

// ---------------- fp32 -> (bf16 hi, bf16 lo [, fp16]) split ----------------
__global__ void split_hl(const float* __restrict__ src,
                         __nv_bfloat16* __restrict__ h, __nv_bfloat16* __restrict__ l,
                         __half* __restrict__ f)
{
    const size_t i = ((size_t)blockIdx.x * blockDim.x + threadIdx.x) * 4;
    float4 v = *(const float4*)(src + i);
    __nv_bfloat16 h0 = __float2bfloat16(v.x), h1 = __float2bfloat16(v.y);
    __nv_bfloat16 h2 = __float2bfloat16(v.z), h3 = __float2bfloat16(v.w);
    *(__nv_bfloat162*)(h + i)     = __nv_bfloat162(h0, h1);
    *(__nv_bfloat162*)(h + i + 2) = __nv_bfloat162(h2, h3);
    *(__nv_bfloat162*)(l + i)     = __nv_bfloat162(__float2bfloat16(v.x - __bfloat162float(h0)),
                                                   __float2bfloat16(v.y - __bfloat162float(h1)));
    *(__nv_bfloat162*)(l + i + 2) = __nv_bfloat162(__float2bfloat16(v.z - __bfloat162float(h2)),
                                                   __float2bfloat16(v.w - __bfloat162float(h3)));
    if (f) {
        *(__half2*)(f + i)     = __floats2half2_rn(v.x, v.y);
        *(__half2*)(f + i + 2) = __floats2half2_rn(v.z, v.w);
    }
}

// ---------------- column softmax (axis=1) stats: coalesced via smem transpose ----------------
__global__ __launch_bounds__(256)
void col_stats(const float* __restrict__ S,
               float* __restrict__ cmax, float* __restrict__ crsum)
{
    __shared__ float tile[32][260];
    const int b  = blockIdx.y;
    const int c0 = blockIdx.x * 256;
    const int tid = threadIdx.x;
    const float* Sb = S + (size_t)b * NN * NN + c0;

    float m = -1e30f, s = 0.0f;
    for (int rt = 0; rt < NN / 32; rt++) {
        const float* base = Sb + (size_t)rt * 32 * NN;
#pragma unroll
        for (int i = 0; i < 8; i++) {
            const int idx = i * 256 + tid;
            const int r   = idx >> 6;
            const int c4  = (idx & 63) << 2;
            *(float4*)&tile[r][c4] = *(const float4*)(base + (size_t)r * NN + c4);
        }
        __syncthreads();
#pragma unroll
        for (int r = 0; r < 32; r++) {
            const float v = tile[r][tid];
            if (v > m) {
                const float d = m - v;
                s = (d < -20.0f) ? 1.0f : s * __expf(d) + 1.0f;
                m = v;
            } else {
                const float d = v - m;
                if (d > -20.0f) s += __expf(d);
            }
        }
        __syncthreads();
    }
    cmax[b * NN + c0 + tid]  = m;
    crsum[b * NN + c0 + tid] = 1.0f / s;
}

// attn (fp16) = exp(S - cmax[j]) * crsum[j]
__global__ void col_norm_f16(const float* __restrict__ S,
                             const float* __restrict__ cmax, const float* __restrict__ crsum,
                             __half* __restrict__ af)
{
    const int b   = blockIdx.y;
    const int lin = blockIdx.x * blockDim.x + threadIdx.x;
    const int i   = lin >> 9;
    const int j4  = (lin & 511) << 2;
    const size_t off = (size_t)b * NN * NN + (size_t)i * NN + j4;

    float4 v  = *(const float4*)(S + off);
    float4 mx = *(const float4*)(cmax  + b * NN + j4);
    float4 rs = *(const float4*)(crsum + b * NN + j4);
    float a0 = __expf(v.x - mx.x) * rs.x;
    float a1 = __expf(v.y - mx.y) * rs.y;
    float a2 = __expf(v.z - mx.z) * rs.z;
    float a3 = __expf(v.w - mx.w) * rs.w;
    *(__half2*)(af + off)     = __floats2half2_rn(a0, a1);
    *(__half2*)(af + off + 2) = __floats2half2_rn(a2, a3);
}

// ---------------- launch ----------------
extern "C" void kernel_launch(void* const* d_in, const int* in_sizes, int n_in,
                              void* d_out, int out_size)
{
    const float* X = (const float*)d_in[0];
    const float* W = (const float*)d_in[1];
    // d_in[2] = bias: per-column constant on scores -> cancels in axis-1 softmax.
    // d_in[3] = gamma: scalar constant -> cancels likewise. Both unused.
    float* out = (float*)d_out;

    __nv_bfloat16 *xh, *xl, *wh, *wl, *qh, *ql;
    __half *xf, *afp;
    float *s, *cmax, *csum;
    cudaGetSymbolAddress((void**)&xh, g_xh);  cudaGetSymbolAddress((void**)&xl, g_xl);
    cudaGetSymbolAddress((void**)&xf, g_xf);
    cudaGetSymbolAddress((void**)&wh, g_wh);  cudaGetSymbolAddress((void**)&wl, g_wl);
    cudaGetSymbolAddress((void**)&qh, g_qh);  cudaGetSymbolAddress((void**)&ql, g_ql);
    cudaGetSymbolAddress((void**)&afp, g_af);
    cudaGetSymbolAddress((void**)&s,  g_s);
    cudaGetSymbolAddress((void**)&cmax, g_cmax);
    cudaGetSymbolAddress((void**)&csum, g_csum);

    int dev = 0;  cudaGetDevice(&dev);
    int nsm = 148;
    cudaDeviceGetAttribute(&nsm, cudaDevAttrMultiProcessorCount, dev);

    const int smem = NSTG * STAGE_BYTES;   // 96 KB -> 2 CTAs/SM
    cudaFuncSetAttribute(gemm_mma<false>, cudaFuncAttributeMaxDynamicSharedMemorySize, smem);
    cudaFuncSetAttribute(gemm_mma<true>,  cudaFuncAttributeMaxDynamicSharedMemorySize, smem);

    // split inputs: X -> bf16 hi/lo + fp16; W -> bf16 hi/lo
    split_hl<<<(BATCH * NN * EE / 4) / 256, 256>>>(X, xh, xl, xf);
    split_hl<<<(EE * EE / 4) / 256, 256>>>(W, wh, wl, nullptr);

    const long long sXE = (long long)NN * EE;
    const long long sNN = (long long)NN * NN;
    const int grid = 2 * nsm;

    // GEMM1: Q = X W^T -> hi/lo bf16. 3-phase bf16. Tiles: gx=16, gy=128 -> 2048.
    gemm_mma<false><<<grid, 128, smem>>>(xh, xl, wh, wl, 0, 0, 0,
                                         nullptr, qh, ql, 1, 16, 128, 2048, 96);

    // GEMM2: S[b] = Q[b] X[b]^T (fp32). 3-phase bf16. Tiles: gx=16, gy=16, gz=8 -> 2048.
    gemm_mma<false><<<grid, 128, smem>>>(qh, ql, xh, xl, sXE, sXE, sNN,
                                         s, nullptr, nullptr, 0, 16, 16, 2048, 96);

    // softmax over axis=1 (columns), write fp16 attn
    col_stats<<<dim3(NN / 256, BATCH), 256>>>(s, cmax, csum);
    col_norm_f16<<<dim3((NN * NN / 4) / 256, BATCH), 256>>>(s, cmax, csum, afp);

    // GEMM3: out[b] = X[b] Attn[b]^T (fp32). Single-phase fp16 (downstream of softmax).
    gemm_mma<true><<<grid, 128, smem>>>(xf, xf, afp, afp, sXE, sNN, sNN,
                                        out, nullptr, nullptr, 0, 16, 16, 2048, 32);
}

// round 10
// speedup vs baseline: 1.1291x; 1.1291x over previous
#include <cuda_runtime.h>
#include <cuda_bf16.h>
#include <cuda_fp16.h>
#include <cstdint>

#define BATCH 8
#define NN 2048
#define EE 2048

#define BM 256
#define BN 128
#define STAGES 4
#define STAGE_BYTES 49152       // A: 256x128B (32KB) + B: 128x128B (16KB)
#define STAT_BYTES 4096         // 512 x float2 column-stat scratch

// ---------------- scratch globals (no cudaMalloc allowed) ----------------
__device__ __align__(256) __nv_bfloat16 g_xh[(size_t)BATCH * NN * EE];
__device__ __align__(256) __nv_bfloat16 g_xl[(size_t)BATCH * NN * EE];
__device__ __align__(256) __half        g_xf[(size_t)BATCH * NN * EE];
__device__ __align__(256) __nv_bfloat16 g_wh[(size_t)EE * EE];
__device__ __align__(256) __nv_bfloat16 g_wl[(size_t)EE * EE];
__device__ __align__(256) __nv_bfloat16 g_qh[(size_t)BATCH * NN * EE];
__device__ __align__(256) __nv_bfloat16 g_ql[(size_t)BATCH * NN * EE];
__device__ __align__(256) __half        g_af[(size_t)BATCH * NN * NN];
__device__ __align__(256) float         g_s [(size_t)BATCH * NN * NN];
__device__ __align__(256) float         g_pm[BATCH * 8 * NN];   // per-rowtile col max
__device__ __align__(256) float         g_ps[BATCH * 8 * NN];   // per-rowtile col sum
__device__ __align__(256) float         g_cmax[BATCH * NN];
__device__ __align__(256) float         g_csum[BATCH * NN];

// ---------------- helpers ----------------
__device__ __forceinline__ uint32_t smem_u32(const void* p) {
    uint32_t a;
    asm("{ .reg .u64 t; cvta.to.shared.u64 t, %1; cvt.u32.u64 %0, t; }" : "=r"(a) : "l"(p));
    return a;
}
__device__ __forceinline__ void cp16(uint32_t s, const void* g) {
    asm volatile("cp.async.cg.shared.global [%0], [%1], 16;" :: "r"(s), "l"(g) : "memory");
}
__device__ __forceinline__ void cp_commit() {
    asm volatile("cp.async.commit_group;" ::: "memory");
}
template <int N> __device__ __forceinline__ void cp_wait() {
    asm volatile("cp.async.wait_group %0;" :: "n"(N) : "memory");
}
__device__ __forceinline__ void ldm4(uint32_t* r, uint32_t a) {
    asm volatile("ldmatrix.sync.aligned.m8n8.x4.shared.b16 {%0,%1,%2,%3}, [%4];"
                 : "=r"(r[0]), "=r"(r[1]), "=r"(r[2]), "=r"(r[3]) : "r"(a));
}
template <bool F16>
__device__ __forceinline__ void mma16816(float* c, const uint32_t* a, uint32_t b0, uint32_t b1) {
    if (F16)
        asm volatile(
            "mma.sync.aligned.m16n8k16.row.col.f32.f16.f16.f32 "
            "{%0,%1,%2,%3}, {%4,%5,%6,%7}, {%8,%9}, {%0,%1,%2,%3};"
            : "+f"(c[0]), "+f"(c[1]), "+f"(c[2]), "+f"(c[3])
            : "r"(a[0]), "r"(a[1]), "r"(a[2]), "r"(a[3]), "r"(b0), "r"(b1));
    else
        asm volatile(
            "mma.sync.aligned.m16n8k16.row.col.f32.bf16.bf16.f32 "
            "{%0,%1,%2,%3}, {%4,%5,%6,%7}, {%8,%9}, {%0,%1,%2,%3};"
            : "+f"(c[0]), "+f"(c[1]), "+f"(c[2]), "+f"(c[3])
            : "r"(a[0]), "r"(a[1]), "r"(a[2]), "r"(a[3]), "r"(b0), "r"(b1));
}

// ---------------- persistent tensor-core GEMM: C tiles 256x128 = A @ B^T ----------------
// Phases over K' = NBK*64: kbn>>5 selects (Ah,Bh) / (Al,Bh) / (Ah,Bl).
// NBK=96: 3-phase split GEMM.  NBK=32: single-phase.
// mode 0: fp32 out (+ per-tile column softmax stats when pm!=null).
// mode 1: split-store hi/lo bf16 to outH/outL.
template <bool F16, int NBK>
__global__ __launch_bounds__(256, 1)
void gemm_mma(const void* Ahv, const void* Alv, const void* Bhv, const void* Blv,
              long long aBatch, long long bBatch, long long cBatch,
              float* outF, __nv_bfloat16* outH, __nv_bfloat16* outL, int mode,
              int gx, int gy, int nTiles, float* pm, float* ps)
{
    extern __shared__ __align__(128) char smem[];
    const uint32_t stg0 = smem_u32(smem);
    const int tid  = threadIdx.x;
    const int lane = tid & 31;
    const int warp = tid >> 5;

    // -------- global->smem producer mapping (all 256 threads) --------
    const int lr = tid >> 3;        // 0..31 row group
    const int lc = tid & 7;         // 16B chunk within 128B row
    const uint32_t so = (uint32_t)(lr * 128 + ((lc ^ (lr & 7)) << 4));

    // -------- mma fragment addressing precompute --------
    const int wm  = warp & 3;            // 4 warps down M (64 rows each)
    const int wn  = warp >> 2;           // 2 warps across N (64 cols each)
    const int m0w = wm * 64;
    const int n0w = wn * 64;
    const uint32_t aRow  = (uint32_t)(m0w + (lane & 15));
    const uint32_t aBase = aRow * 128;
    const uint32_t aXor  = aRow & 7;
    const uint32_t ac0   = (uint32_t)(lane >> 4);
    const uint32_t bRow  = (uint32_t)(n0w + ((lane >> 4) << 3) + (lane & 7));
    const uint32_t bBase = 32768u + bRow * 128;
    const uint32_t bXor  = (uint32_t)(lane & 7);
    const uint32_t bc0   = (uint32_t)((lane >> 3) & 1);

    float acc[4][8][4] = {};
    uint32_t af[2][4][4], bf[2][4][4];   // double-buffered fragments

    // load-side pointers (switch to next tile 3 k-blocks early)
    const char *gAh, *gAl, *gBh, *gBl;
    auto setLoad = [&](int t) {
        const int bx = t % gx;
        const int r2 = t / gx;
        const int by = r2 % gy;
        const int bz = r2 / gy;
        const size_t aoff = ((size_t)bz * (size_t)aBatch + (size_t)(by * BM + lr) * EE) * 2 + lc * 16;
        const size_t boff = ((size_t)bz * (size_t)bBatch + (size_t)(bx * BN + lr) * EE) * 2 + lc * 16;
        gAh = (const char*)Ahv + aoff;
        gAl = (const char*)Alv + aoff;
        gBh = (const char*)Bhv + boff;
        gBl = (const char*)Blv + boff;
    };

    // one quarter of a stage load (3 cp16 per thread); part 3 commits the group
    auto load_chunk = [&](int s, int kbn, int part) {
        const int p = kbn >> 5;
        const char* a = (p == 1) ? gAl : gAh;
        const char* b = (p == 2) ? gBl : gBh;
        const uint32_t koff = (uint32_t)(kbn & 31) * 128;
        const uint32_t dstA = stg0 + (uint32_t)s * STAGE_BYTES + so;
        const uint32_t dstB = dstA + 32768u;
        cp16(dstA + (uint32_t)(part * 2)     * 4096u, a + koff + (size_t)(part * 2)     * 131072);
        cp16(dstA + (uint32_t)(part * 2 + 1) * 4096u, a + koff + (size_t)(part * 2 + 1) * 131072);
        cp16(dstB + (uint32_t)part           * 4096u, b + koff + (size_t)part           * 131072);
        if (part == 3) cp_commit();
    };
    // fragment load for one ks into buffer bsel from stage base sb_
    auto ldm_ks = [&](uint32_t sb_, uint32_t ke, int bsel) {
#pragma unroll
        for (int mt = 0; mt < 4; mt++)
            ldm4(af[bsel][mt], sb_ + aBase + mt * 2048u + (((ke * 2 + ac0) ^ aXor) << 4));
#pragma unroll
        for (int np = 0; np < 4; np++)
            ldm4(bf[bsel][np], sb_ + bBase + np * 2048u + (((ke * 2 + bc0) ^ bXor) << 4));
    };

    int t = blockIdx.x;
    if (t >= nTiles) return;
    setLoad(t);
#pragma unroll
    for (int st = 0; st < 3; st++)
        for (int part = 0; part < 4; part++) load_chunk(st, st, part);
    cp_wait<1>();                 // stages 0 and 1 complete
    __syncthreads();
    ldm_ks(stg0, 0, 0);           // fragments for kb=0, ks=0

    for (;;) {
        // epilogue coords of the CURRENT tile
        const int bx = t % gx;
        const int r2 = t / gx;
        const int row0 = (r2 % gy) * BM;
        const int col0 = bx * BN;
        const int z    = r2 / gy;
        const bool hasNext = (t + (int)gridDim.x) < nTiles;

        for (int kb = 0; kb < NBK; kb++) {
            if (kb == NBK - 3 && hasNext) setLoad(t + (int)gridDim.x);
            const bool doLoad = (kb < NBK - 3) || hasNext;
            const int  kbn    = (kb + 3 < NBK) ? (kb + 3) : (kb + 3 - NBK);
            const uint32_t sb = stg0 + (uint32_t)(kb & 3) * STAGE_BYTES;
#pragma unroll
            for (int ks = 0; ks < 4; ks++) {
                if (doLoad) load_chunk((kb + 3) & 3, kbn, ks);
                const int cur = ks & 1;
                if (ks < 3)
                    ldm_ks(sb, (uint32_t)ks + 1, cur ^ 1);
                else if (kb + 1 < NBK)
                    ldm_ks(stg0 + (uint32_t)((kb + 1) & 3) * STAGE_BYTES, 0, cur ^ 1);
#pragma unroll
                for (int mt = 0; mt < 4; mt++)
#pragma unroll
                    for (int np = 0; np < 4; np++) {
                        mma16816<F16>(acc[mt][np * 2],     af[cur][mt], bf[cur][np][0], bf[cur][np][1]);
                        mma16816<F16>(acc[mt][np * 2 + 1], af[cur][mt], bf[cur][np][2], bf[cur][np][3]);
                    }
            }
            if (kb + 1 < NBK) {
                if (doLoad) cp_wait<1>(); else cp_wait<0>();
                __syncthreads();
            }
        }
        if (hasNext) cp_wait<1>(); else cp_wait<0>();
        __syncthreads();
        if (hasNext) ldm_ks(stg0, 0, 0);   // next tile kb0/ks0 fragments (stage 0)

        // -------- epilogue (overlaps with in-flight next-tile cp.async) --------
        const int g  = lane >> 2;
        const int tg = lane & 3;
        if (mode == 0) {
            float* base = outF + (size_t)z * (size_t)cBatch;
#pragma unroll
            for (int mt = 0; mt < 4; mt++) {
                const int rg = row0 + m0w + mt * 16 + g;
#pragma unroll
                for (int nt = 0; nt < 8; nt++) {
                    const int cg = col0 + n0w + nt * 8 + 2 * tg;
                    *(float2*)(base + (size_t)rg * 2048 + cg)       = make_float2(acc[mt][nt][0], acc[mt][nt][1]);
                    *(float2*)(base + (size_t)(rg + 8) * 2048 + cg) = make_float2(acc[mt][nt][2], acc[mt][nt][3]);
                }
            }
            if (pm) {
                // per-tile column softmax stats: (max, sum exp) over this tile's 256 rows.
                float2* sst = (float2*)(smem + STAGES * STAGE_BYTES);
#pragma unroll
                for (int nt = 0; nt < 8; nt++) {
#pragma unroll
                    for (int p = 0; p < 2; p++) {
                        float m = acc[0][nt][p];
#pragma unroll
                        for (int mt = 0; mt < 4; mt++) {
                            m = fmaxf(m, acc[mt][nt][p]);
                            m = fmaxf(m, acc[mt][nt][2 + p]);
                        }
                        float s = 0.0f;
#pragma unroll
                        for (int mt = 0; mt < 4; mt++) {
                            s += __expf(acc[mt][nt][p]     - m);
                            s += __expf(acc[mt][nt][2 + p] - m);
                        }
                        // reduce over g (lanes xor 4,8,16); tg lanes stay separate
#pragma unroll
                        for (int off = 4; off < 32; off <<= 1) {
                            float om = __shfl_xor_sync(0xffffffffu, m, off);
                            float os = __shfl_xor_sync(0xffffffffu, s, off);
                            if (om > m) { s = s * __expf(m - om) + os; m = om; }
                            else        { s += os * __expf(om - m); }
                        }
                        if (lane < 4) {   // lane == tg representative
                            const int colLocal = n0w + nt * 8 + lane * 2 + p;
                            sst[colLocal * 4 + wm] = make_float2(m, s);
                        }
                    }
                }
                __syncthreads();
                if (tid < 128) {   // one thread per column: combine 4 wm partials
                    float2 a0 = sst[tid * 4 + 0];
                    float2 a1 = sst[tid * 4 + 1];
                    float2 a2 = sst[tid * 4 + 2];
                    float2 a3 = sst[tid * 4 + 3];
                    float M = fmaxf(fmaxf(a0.x, a1.x), fmaxf(a2.x, a3.x));
                    float S = a0.y * __expf(a0.x - M) + a1.y * __expf(a1.x - M)
                            + a2.y * __expf(a2.x - M) + a3.y * __expf(a3.x - M);
                    const size_t o = ((size_t)z * (size_t)gy + (size_t)(row0 / BM)) * NN
                                   + (size_t)(col0 + tid);
                    pm[o] = M;
                    ps[o] = S;
                }
            }
        } else {
#pragma unroll
            for (int mt = 0; mt < 4; mt++) {
                const int rg = row0 + m0w + mt * 16 + g;
#pragma unroll
                for (int nt = 0; nt < 8; nt++) {
                    const int cg = col0 + n0w + nt * 8 + 2 * tg;
                    float v[4] = {acc[mt][nt][0], acc[mt][nt][1], acc[mt][nt][2], acc[mt][nt][3]};
                    __nv_bfloat16 h0 = __float2bfloat16(v[0]), h1 = __float2bfloat16(v[1]);
                    __nv_bfloat16 h2 = __float2bfloat16(v[2]), h3 = __float2bfloat16(v[3]);
                    __nv_bfloat16 l0 = __float2bfloat16(v[0] - __bfloat162float(h0));
                    __nv_bfloat16 l1 = __float2bfloat16(v[1] - __bfloat162float(h1));
                    __nv_bfloat16 l2 = __float2bfloat16(v[2] - __bfloat162float(h2));
                    __nv_bfloat16 l3 = __float2bfloat16(v[3] - __bfloat162float(h3));
                    *(__nv_bfloat162*)(outH + (size_t)rg * 2048 + cg)       = __nv_bfloat162(h0, h1);
                    *(__nv_bfloat162*)(outL + (size_t)rg * 2048 + cg)       = __nv_bfloat162(l0, l1);
                    *(__nv_bfloat162*)(outH + (size_t)(rg + 8) * 2048 + cg) = __nv_bfloat162(h2, h3);
                    *(__nv_bfloat162*)(outL + (size_t)(rg + 8) * 2048 + cg) = __nv_bfloat162(l2, l3);
                }
            }
        }
        if (!hasNext) break;
#pragma unroll
        for (int mt = 0; mt < 4; mt++)
#pragma unroll
            for (int nt = 0; nt < 8; nt++)
#pragma unroll
                for (int q = 0; q < 4; q++) acc[mt][nt][q] = 0.0f;
        t += (int)gridDim.x;
    }
}

// ---------------- fused split: X -> bf16 hi/lo + fp16, W -> bf16 hi/lo ----------------
__global__ void split_all(const float* __restrict__ X, const float* __restrict__ W,
                          __nv_bfloat16* __restrict__ xh, __nv_bfloat16* __restrict__ xl,
                          __half* __restrict__ xf,
                          __nv_bfloat16* __restrict__ wh, __nv_bfloat16* __restrict__ wl)
{
    const size_t q  = (size_t)blockIdx.x * blockDim.x + threadIdx.x;
    const size_t XQ = (size_t)BATCH * NN * EE / 4;
    if (q < XQ) {
        const size_t i = q * 4;
        float4 v = *(const float4*)(X + i);
        __nv_bfloat16 h0 = __float2bfloat16(v.x), h1 = __float2bfloat16(v.y);
        __nv_bfloat16 h2 = __float2bfloat16(v.z), h3 = __float2bfloat16(v.w);
        *(__nv_bfloat162*)(xh + i)     = __nv_bfloat162(h0, h1);
        *(__nv_bfloat162*)(xh + i + 2) = __nv_bfloat162(h2, h3);
        *(__nv_bfloat162*)(xl + i)     = __nv_bfloat162(__float2bfloat16(v.x - __bfloat162float(h0)),
                                                        __float2bfloat16(v.y - __bfloat162float(h1)));
        *(__nv_bfloat162*)(xl + i + 2) = __nv_bfloat162(__float2bfloat16(v.z - __bfloat162float(h2)),
                                                        __float2bfloat16(v.w - __bfloat162float(h3)));
        *(__half2*)(xf + i)     = __floats2half2_rn(v.x, v.y);
        *(__half2*)(xf + i + 2) = __floats2half2_rn(v.z, v.w);
    } else {
        const size_t i = (q - XQ) * 4;
        float4 v = *(const float4*)(W + i);
        __nv_bfloat16 h0 = __float2bfloat16(v.x), h1 = __float2bfloat16(v.y);
        __nv_bfloat16 h2 = __float2bfloat16(v.z), h3 = __float2bfloat16(v.w);
        *(__nv_bfloat162*)(wh + i)     = __nv_bfloat162(h0, h1);
        *(__nv_bfloat162*)(wh + i + 2) = __nv_bfloat162(h2, h3);
        *(__nv_bfloat162*)(wl + i)     = __nv_bfloat162(__float2bfloat16(v.x - __bfloat162float(h0)),
                                                        __float2bfloat16(v.y - __bfloat162float(h1)));
        *(__nv_bfloat162*)(wl + i + 2) = __nv_bfloat162(__float2bfloat16(v.z - __bfloat162float(h2)),
                                                        __float2bfloat16(v.w - __bfloat162float(h3)));
    }
}

// ---------------- combine per-tile column stats -> cmax, 1/sum ----------------
__global__ void col_finish(const float* __restrict__ pm, const float* __restrict__ ps,
                           float* __restrict__ cmax, float* __restrict__ crsum)
{
    const int i = blockIdx.x * blockDim.x + threadIdx.x;   // b*2048 + col
    const int b = i >> 11, col = i & 2047;
    const float* pmb = pm + (size_t)b * 8 * NN + col;
    const float* psb = ps + (size_t)b * 8 * NN + col;
    float M = pmb[0], S = psb[0];
#pragma unroll
    for (int t2 = 1; t2 < 8; t2++) {
        const float m = pmb[(size_t)t2 * NN], s = psb[(size_t)t2 * NN];
        if (m > M) { S = S * __expf(M - m) + s; M = m; }
        else       { S += s * __expf(m - M); }
    }
    cmax[i]  = M;
    crsum[i] = 1.0f / S;
}

// attn (fp16) = exp(S - cmax[j]) * crsum[j]
__global__ void col_norm_f16(const float* __restrict__ S,
                             const float* __restrict__ cmax, const float* __restrict__ crsum,
                             __half* __restrict__ af)
{
    const int b   = blockIdx.y;
    const int lin = blockIdx.x * blockDim.x + threadIdx.x;
    const int i   = lin >> 9;
    const int j4  = (lin & 511) << 2;
    const size_t off = (size_t)b * NN * NN + (size_t)i * NN + j4;

    float4 v  = *(const float4*)(S + off);
    float4 mx = *(const float4*)(cmax  + b * NN + j4);
    float4 rs = *(const float4*)(crsum + b * NN + j4);
    float a0 = __expf(v.x - mx.x) * rs.x;
    float a1 = __expf(v.y - mx.y) * rs.y;
    float a2 = __expf(v.z - mx.z) * rs.z;
    float a3 = __expf(v.w - mx.w) * rs.w;
    *(__half2*)(af + off)     = __floats2half2_rn(a0, a1);
    *(__half2*)(af + off + 2) = __floats2half2_rn(a2, a3);
}

// ---------------- launch ----------------
extern "C" void kernel_launch(void* const* d_in, const int* in_sizes, int n_in,
                              void* d_out, int out_size)
{
    const float* X = (const float*)d_in[0];
    const float* W = (const float*)d_in[1];
    // d_in[2] = bias: per-column constant on scores -> cancels in axis-1 softmax.
    // d_in[3] = gamma: scalar constant -> cancels likewise. Both unused.
    float* out = (float*)d_out;

    __nv_bfloat16 *xh, *xl, *wh, *wl, *qh, *ql;
    __half *xf, *afp;
    float *s, *pm, *ps, *cmax, *csum;
    cudaGetSymbolAddress((void**)&xh, g_xh);  cudaGetSymbolAddress((void**)&xl, g_xl);
    cudaGetSymbolAddress((void**)&xf, g_xf);
    cudaGetSymbolAddress((void**)&wh, g_wh);  cudaGetSymbolAddress((void**)&wl, g_wl);
    cudaGetSymbolAddress((void**)&qh, g_qh);  cudaGetSymbolAddress((void**)&ql, g_ql);
    cudaGetSymbolAddress((void**)&afp, g_af);
    cudaGetSymbolAddress((void**)&s,  g_s);
    cudaGetSymbolAddress((void**)&pm, g_pm);  cudaGetSymbolAddress((void**)&ps, g_ps);
    cudaGetSymbolAddress((void**)&cmax, g_cmax);
    cudaGetSymbolAddress((void**)&csum, g_csum);

    int dev = 0;  cudaGetDevice(&dev);
    int nsm = 148;
    cudaDeviceGetAttribute(&nsm, cudaDevAttrMultiProcessorCount, dev);

    const int smem = STAGES * STAGE_BYTES + STAT_BYTES;   // 196.6KB + 4KB -> 1 CTA/SM
    cudaFuncSetAttribute((const void*)gemm_mma<false, 96>, cudaFuncAttributeMaxDynamicSharedMemorySize, smem);
    cudaFuncSetAttribute((const void*)gemm_mma<true, 32>,  cudaFuncAttributeMaxDynamicSharedMemorySize, smem);

    // split inputs (one launch): X -> bf16 hi/lo + fp16; W -> bf16 hi/lo
    {
        const size_t quads = ((size_t)BATCH * NN * EE + (size_t)EE * EE) / 4;
        split_all<<<(int)(quads / 256), 256>>>(X, W, xh, xl, xf, wh, wl);
    }

    const long long sXE = (long long)NN * EE;
    const long long sNN = (long long)NN * NN;

    // GEMM1: Q = X W^T -> hi/lo bf16. 3-phase bf16. Tiles: gx=16, gy=64.
    gemm_mma<false, 96><<<nsm, 256, smem>>>(xh, xl, wh, wl, 0, 0, 0,
                                            nullptr, qh, ql, 1, 16, 64, 1024,
                                            nullptr, nullptr);

    // GEMM2: S[b] = Q[b] X[b]^T (fp32) + fused per-tile column stats.
    gemm_mma<false, 96><<<nsm, 256, smem>>>(qh, ql, xh, xl, sXE, sXE, sNN,
                                            s, nullptr, nullptr, 0, 16, 8, 1024,
                                            pm, ps);

    // combine stats, then normalize to fp16 attn
    col_finish<<<(BATCH * NN) / 256, 256>>>(pm, ps, cmax, csum);
    col_norm_f16<<<dim3((NN * NN / 4) / 256, BATCH), 256>>>(s, cmax, csum, afp);

    // GEMM3: out[b] = X[b] Attn[b]^T (fp32). Single-phase fp16 (downstream of softmax).
    gemm_mma<true, 32><<<nsm, 256, smem>>>(xf, xf, afp, afp, sXE, sNN, sNN,
                                           out, nullptr, nullptr, 0, 16, 8, 1024,
                                           nullptr, nullptr);
}

// round 11
// speedup vs baseline: 1.1439x; 1.0130x over previous
#include <cuda_runtime.h>
#include <cuda_bf16.h>
#include <cuda_fp16.h>
#include <cstdint>

#define BATCH 8
#define NN 2048
#define EE 2048

#define BM 256
#define BN 128
#define STAGES 4
#define STAGE_BYTES 49152       // A: 256x128B (32KB) + B: 128x128B (16KB)
#define STAT_BYTES 4096         // 512 x float2 column-stat scratch
#define CAP 2048                // per-row sparse capacity (cannot overflow)

// ---------------- scratch globals (no cudaMalloc allowed) ----------------
__device__ __align__(256) __nv_bfloat16 g_xh[(size_t)BATCH * NN * EE];
__device__ __align__(256) __nv_bfloat16 g_xl[(size_t)BATCH * NN * EE];
__device__ __align__(256) float         g_xt[(size_t)BATCH * NN * EE];   // X^T per batch [e][n]
__device__ __align__(256) __nv_bfloat16 g_wh[(size_t)EE * EE];
__device__ __align__(256) __nv_bfloat16 g_wl[(size_t)EE * EE];
__device__ __align__(256) __nv_bfloat16 g_qh[(size_t)BATCH * NN * EE];
__device__ __align__(256) __nv_bfloat16 g_ql[(size_t)BATCH * NN * EE];
__device__ __align__(256) float         g_s [(size_t)BATCH * NN * NN];
__device__ __align__(256) float         g_pm[BATCH * 8 * NN];
__device__ __align__(256) float         g_ps[BATCH * 8 * NN];
__device__ __align__(256) float         g_cmax[BATCH * NN];
__device__ __align__(256) float         g_csum[BATCH * NN];
__device__ __align__(256) int           g_cnt[BATCH * NN];
__device__ __align__(256) uint2         g_ent[(size_t)BATCH * NN * CAP]; // (e, w bits)

// ---------------- helpers ----------------
__device__ __forceinline__ uint32_t smem_u32(const void* p) {
    uint32_t a;
    asm("{ .reg .u64 t; cvta.to.shared.u64 t, %1; cvt.u32.u64 %0, t; }" : "=r"(a) : "l"(p));
    return a;
}
__device__ __forceinline__ void cp16(uint32_t s, const void* g) {
    asm volatile("cp.async.cg.shared.global [%0], [%1], 16;" :: "r"(s), "l"(g) : "memory");
}
__device__ __forceinline__ void cp_commit() {
    asm volatile("cp.async.commit_group;" ::: "memory");
}
template <int N> __device__ __forceinline__ void cp_wait() {
    asm volatile("cp.async.wait_group %0;" :: "n"(N) : "memory");
}
__device__ __forceinline__ void ldm4(uint32_t* r, uint32_t a) {
    asm volatile("ldmatrix.sync.aligned.m8n8.x4.shared.b16 {%0,%1,%2,%3}, [%4];"
                 : "=r"(r[0]), "=r"(r[1]), "=r"(r[2]), "=r"(r[3]) : "r"(a));
}
__device__ __forceinline__ void mma16816(float* c, const uint32_t* a, uint32_t b0, uint32_t b1) {
    asm volatile(
        "mma.sync.aligned.m16n8k16.row.col.f32.bf16.bf16.f32 "
        "{%0,%1,%2,%3}, {%4,%5,%6,%7}, {%8,%9}, {%0,%1,%2,%3};"
        : "+f"(c[0]), "+f"(c[1]), "+f"(c[2]), "+f"(c[3])
        : "r"(a[0]), "r"(a[1]), "r"(a[2]), "r"(a[3]), "r"(b0), "r"(b1));
}

// ---------------- persistent tensor-core GEMM: C tiles 256x128 = A @ B^T ----------------
// 3-phase bf16 split over K'=96*64: (Ah,Bh) / (Al,Bh) / (Ah,Bl).
// mode 0: fp32 out (+ per-tile column softmax stats when pm!=null).
// mode 1: split-store hi/lo bf16 to outH/outL.
template <int NBK>
__global__ __launch_bounds__(256, 1)
void gemm_mma(const void* Ahv, const void* Alv, const void* Bhv, const void* Blv,
              long long aBatch, long long bBatch, long long cBatch,
              float* outF, __nv_bfloat16* outH, __nv_bfloat16* outL, int mode,
              int gx, int gy, int nTiles, float* pm, float* ps)
{
    extern __shared__ __align__(128) char smem[];
    const uint32_t stg0 = smem_u32(smem);
    const int tid  = threadIdx.x;
    const int lane = tid & 31;
    const int warp = tid >> 5;

    const int lr = tid >> 3;
    const int lc = tid & 7;
    const uint32_t so = (uint32_t)(lr * 128 + ((lc ^ (lr & 7)) << 4));

    const int wm  = warp & 3;
    const int wn  = warp >> 2;
    const int m0w = wm * 64;
    const int n0w = wn * 64;
    const uint32_t aRow  = (uint32_t)(m0w + (lane & 15));
    const uint32_t aBase = aRow * 128;
    const uint32_t aXor  = aRow & 7;
    const uint32_t ac0   = (uint32_t)(lane >> 4);
    const uint32_t bRow  = (uint32_t)(n0w + ((lane >> 4) << 3) + (lane & 7));
    const uint32_t bBase = 32768u + bRow * 128;
    const uint32_t bXor  = (uint32_t)(lane & 7);
    const uint32_t bc0   = (uint32_t)((lane >> 3) & 1);

    float acc[4][8][4] = {};
    uint32_t af[2][4][4], bf[2][4][4];

    const char *gAh, *gAl, *gBh, *gBl;
    auto setLoad = [&](int t) {
        const int bx = t % gx;
        const int r2 = t / gx;
        const int by = r2 % gy;
        const int bz = r2 / gy;
        const size_t aoff = ((size_t)bz * (size_t)aBatch + (size_t)(by * BM + lr) * EE) * 2 + lc * 16;
        const size_t boff = ((size_t)bz * (size_t)bBatch + (size_t)(bx * BN + lr) * EE) * 2 + lc * 16;
        gAh = (const char*)Ahv + aoff;
        gAl = (const char*)Alv + aoff;
        gBh = (const char*)Bhv + boff;
        gBl = (const char*)Blv + boff;
    };

    auto load_chunk = [&](int s, int kbn, int part) {
        const int p = kbn >> 5;
        const char* a = (p == 1) ? gAl : gAh;
        const char* b = (p == 2) ? gBl : gBh;
        const uint32_t koff = (uint32_t)(kbn & 31) * 128;
        const uint32_t dstA = stg0 + (uint32_t)s * STAGE_BYTES + so;
        const uint32_t dstB = dstA + 32768u;
        cp16(dstA + (uint32_t)(part * 2)     * 4096u, a + koff + (size_t)(part * 2)     * 131072);
        cp16(dstA + (uint32_t)(part * 2 + 1) * 4096u, a + koff + (size_t)(part * 2 + 1) * 131072);
        cp16(dstB + (uint32_t)part           * 4096u, b + koff + (size_t)part           * 131072);
        if (part == 3) cp_commit();
    };
    auto ldm_ks = [&](uint32_t sb_, uint32_t ke, int bsel) {
#pragma unroll
        for (int mt = 0; mt < 4; mt++)
            ldm4(af[bsel][mt], sb_ + aBase + mt * 2048u + (((ke * 2 + ac0) ^ aXor) << 4));
#pragma unroll
        for (int np = 0; np < 4; np++)
            ldm4(bf[bsel][np], sb_ + bBase + np * 2048u + (((ke * 2 + bc0) ^ bXor) << 4));
    };

    int t = blockIdx.x;
    if (t >= nTiles) return;
    setLoad(t);
#pragma unroll
    for (int st = 0; st < 3; st++)
        for (int part = 0; part < 4; part++) load_chunk(st, st, part);
    cp_wait<1>();
    __syncthreads();
    ldm_ks(stg0, 0, 0);

    for (;;) {
        const int bx = t % gx;
        const int r2 = t / gx;
        const int row0 = (r2 % gy) * BM;
        const int col0 = bx * BN;
        const int z    = r2 / gy;
        const bool hasNext = (t + (int)gridDim.x) < nTiles;

        for (int kb = 0; kb < NBK; kb++) {
            if (kb == NBK - 3 && hasNext) setLoad(t + (int)gridDim.x);
            const bool doLoad = (kb < NBK - 3) || hasNext;
            const int  kbn    = (kb + 3 < NBK) ? (kb + 3) : (kb + 3 - NBK);
            const uint32_t sb = stg0 + (uint32_t)(kb & 3) * STAGE_BYTES;
#pragma unroll
            for (int ks = 0; ks < 4; ks++) {
                if (doLoad) load_chunk((kb + 3) & 3, kbn, ks);
                const int cur = ks & 1;
                if (ks < 3)
                    ldm_ks(sb, (uint32_t)ks + 1, cur ^ 1);
                else if (kb + 1 < NBK)
                    ldm_ks(stg0 + (uint32_t)((kb + 1) & 3) * STAGE_BYTES, 0, cur ^ 1);
#pragma unroll
                for (int mt = 0; mt < 4; mt++)
#pragma unroll
                    for (int np = 0; np < 4; np++) {
                        mma16816(acc[mt][np * 2],     af[cur][mt], bf[cur][np][0], bf[cur][np][1]);
                        mma16816(acc[mt][np * 2 + 1], af[cur][mt], bf[cur][np][2], bf[cur][np][3]);
                    }
            }
            if (kb + 1 < NBK) {
                if (doLoad) cp_wait<1>(); else cp_wait<0>();
                __syncthreads();
            }
        }
        if (hasNext) cp_wait<1>(); else cp_wait<0>();
        __syncthreads();
        if (hasNext) ldm_ks(stg0, 0, 0);

        // -------- epilogue --------
        const int g  = lane >> 2;
        const int tg = lane & 3;
        if (mode == 0) {
            float* base = outF + (size_t)z * (size_t)cBatch;
#pragma unroll
            for (int mt = 0; mt < 4; mt++) {
                const int rg = row0 + m0w + mt * 16 + g;
#pragma unroll
                for (int nt = 0; nt < 8; nt++) {
                    const int cg = col0 + n0w + nt * 8 + 2 * tg;
                    *(float2*)(base + (size_t)rg * 2048 + cg)       = make_float2(acc[mt][nt][0], acc[mt][nt][1]);
                    *(float2*)(base + (size_t)(rg + 8) * 2048 + cg) = make_float2(acc[mt][nt][2], acc[mt][nt][3]);
                }
            }
            if (pm) {
                float2* sst = (float2*)(smem + STAGES * STAGE_BYTES);
#pragma unroll
                for (int nt = 0; nt < 8; nt++) {
#pragma unroll
                    for (int p = 0; p < 2; p++) {
                        float m = acc[0][nt][p];
#pragma unroll
                        for (int mt = 0; mt < 4; mt++) {
                            m = fmaxf(m, acc[mt][nt][p]);
                            m = fmaxf(m, acc[mt][nt][2 + p]);
                        }
                        float s = 0.0f;
#pragma unroll
                        for (int mt = 0; mt < 4; mt++) {
                            s += __expf(acc[mt][nt][p]     - m);
                            s += __expf(acc[mt][nt][2 + p] - m);
                        }
#pragma unroll
                        for (int off = 4; off < 32; off <<= 1) {
                            float om = __shfl_xor_sync(0xffffffffu, m, off);
                            float os = __shfl_xor_sync(0xffffffffu, s, off);
                            if (om > m) { s = s * __expf(m - om) + os; m = om; }
                            else        { s += os * __expf(om - m); }
                        }
                        if (lane < 4) {
                            const int colLocal = n0w + nt * 8 + lane * 2 + p;
                            sst[colLocal * 4 + wm] = make_float2(m, s);
                        }
                    }
                }
                __syncthreads();
                if (tid < 128) {
                    float2 a0 = sst[tid * 4 + 0];
                    float2 a1 = sst[tid * 4 + 1];
                    float2 a2 = sst[tid * 4 + 2];
                    float2 a3 = sst[tid * 4 + 3];
                    float M = fmaxf(fmaxf(a0.x, a1.x), fmaxf(a2.x, a3.x));
                    float S = a0.y * __expf(a0.x - M) + a1.y * __expf(a1.x - M)
                            + a2.y * __expf(a2.x - M) + a3.y * __expf(a3.x - M);
                    const size_t o = ((size_t)z * (size_t)gy + (size_t)(row0 / BM)) * NN
                                   + (size_t)(col0 + tid);
                    pm[o] = M;
                    ps[o] = S;
                }
            }
        } else {
#pragma unroll
            for (int mt = 0; mt < 4; mt++) {
                const int rg = row0 + m0w + mt * 16 + g;
#pragma unroll
                for (int nt = 0; nt < 8; nt++) {
                    const int cg = col0 + n0w + nt * 8 + 2 * tg;
                    float v[4] = {acc[mt][nt][0], acc[mt][nt][1], acc[mt][nt][2], acc[mt][nt][3]};
                    __nv_bfloat16 h0 = __float2bfloat16(v[0]), h1 = __float2bfloat16(v[1]);
                    __nv_bfloat16 h2 = __float2bfloat16(v[2]), h3 = __float2bfloat16(v[3]);
                    __nv_bfloat16 l0 = __float2bfloat16(v[0] - __bfloat162float(h0));
                    __nv_bfloat16 l1 = __float2bfloat16(v[1] - __bfloat162float(h1));
                    __nv_bfloat16 l2 = __float2bfloat16(v[2] - __bfloat162float(h2));
                    __nv_bfloat16 l3 = __float2bfloat16(v[3] - __bfloat162float(h3));
                    *(__nv_bfloat162*)(outH + (size_t)rg * 2048 + cg)       = __nv_bfloat162(h0, h1);
                    *(__nv_bfloat162*)(outL + (size_t)rg * 2048 + cg)       = __nv_bfloat162(l0, l1);
                    *(__nv_bfloat162*)(outH + (size_t)(rg + 8) * 2048 + cg) = __nv_bfloat162(h2, h3);
                    *(__nv_bfloat162*)(outL + (size_t)(rg + 8) * 2048 + cg) = __nv_bfloat162(l2, l3);
                }
            }
        }
        if (!hasNext) break;
#pragma unroll
        for (int mt = 0; mt < 4; mt++)
#pragma unroll
            for (int nt = 0; nt < 8; nt++)
#pragma unroll
                for (int q = 0; q < 4; q++) acc[mt][nt][q] = 0.0f;
        t += (int)gridDim.x;
    }
}

// ---------------- split: X -> bf16 hi/lo, W -> bf16 hi/lo ----------------
__global__ void split_all(const float* __restrict__ X, const float* __restrict__ W,
                          __nv_bfloat16* __restrict__ xh, __nv_bfloat16* __restrict__ xl,
                          __nv_bfloat16* __restrict__ wh, __nv_bfloat16* __restrict__ wl)
{
    const size_t q  = (size_t)blockIdx.x * blockDim.x + threadIdx.x;
    const size_t XQ = (size_t)BATCH * NN * EE / 4;
    const float* src = (q < XQ) ? X : W;
    __nv_bfloat16* dh = (q < XQ) ? xh : wh;
    __nv_bfloat16* dl = (q < XQ) ? xl : wl;
    const size_t i = (q < XQ) ? q * 4 : (q - XQ) * 4;
    float4 v = *(const float4*)(src + i);
    __nv_bfloat16 h0 = __float2bfloat16(v.x), h1 = __float2bfloat16(v.y);
    __nv_bfloat16 h2 = __float2bfloat16(v.z), h3 = __float2bfloat16(v.w);
    *(__nv_bfloat162*)(dh + i)     = __nv_bfloat162(h0, h1);
    *(__nv_bfloat162*)(dh + i + 2) = __nv_bfloat162(h2, h3);
    *(__nv_bfloat162*)(dl + i)     = __nv_bfloat162(__float2bfloat16(v.x - __bfloat162float(h0)),
                                                    __float2bfloat16(v.y - __bfloat162float(h1)));
    *(__nv_bfloat162*)(dl + i + 2) = __nv_bfloat162(__float2bfloat16(v.z - __bfloat162float(h2)),
                                                    __float2bfloat16(v.w - __bfloat162float(h3)));
}

// ---------------- X transpose (per batch): xt[b][e][n] = X[b][n][e] ----------------
__global__ void transpose_x(const float* __restrict__ X, float* __restrict__ xt)
{
    __shared__ float tile[32][33];
    const int b  = blockIdx.z;
    const int e0 = blockIdx.x * 32;
    const int n0 = blockIdx.y * 32;
    const int c  = threadIdx.x & 31;
    const int r0 = threadIdx.x >> 5;
    const float* Xb  = X  + (size_t)b * NN * EE;
    float*       xtb = xt + (size_t)b * NN * EE;
#pragma unroll
    for (int k = 0; k < 4; k++) {
        const int r = r0 + k * 8;
        tile[r][c] = Xb[(size_t)(n0 + r) * EE + e0 + c];
    }
    __syncthreads();
#pragma unroll
    for (int k = 0; k < 4; k++) {
        const int r = r0 + k * 8;
        xtb[(size_t)(e0 + r) * NN + n0 + c] = tile[c][r];
    }
}

// ---------------- combine per-tile column stats -> cmax, 1/sum ----------------
__global__ void col_finish(const float* __restrict__ pm, const float* __restrict__ ps,
                           float* __restrict__ cmax, float* __restrict__ crsum)
{
    const int i = blockIdx.x * blockDim.x + threadIdx.x;
    const int b = i >> 11, col = i & 2047;
    const float* pmb = pm + (size_t)b * 8 * NN + col;
    const float* psb = ps + (size_t)b * 8 * NN + col;
    float M = pmb[0], S = psb[0];
#pragma unroll
    for (int t2 = 1; t2 < 8; t2++) {
        const float m = pmb[(size_t)t2 * NN], s = psb[(size_t)t2 * NN];
        if (m > M) { S = S * __expf(M - m) + s; M = m; }
        else       { S += s * __expf(m - M); }
    }
    cmax[i]  = M;
    crsum[i] = 1.0f / S;
}

// ---------------- sparse extraction: warp per attn-row (b,m) ----------------
// attn[m,e] = exp(S[m,e]-cmax[e])*crsum[e]; keep entries with S-cmax > -20.
// Dropped mass per column < 2048*e^-20 ~ 4e-6: unconditionally safe.
// Ballot+popc compaction: deterministic order, no atomics. count <= 2048 = CAP.
__global__ __launch_bounds__(256)
void extract(const float* __restrict__ S,
             const float* __restrict__ cmax, const float* __restrict__ crsum,
             int* __restrict__ cnt, uint2* __restrict__ ent)
{
    const int gw   = (int)((blockIdx.x * blockDim.x + threadIdx.x) >> 5);  // b*2048+m
    const int lane = threadIdx.x & 31;
    const int b = gw >> 11;
    const float* Srow = S + (size_t)gw * NN;
    const float* cmb  = cmax  + b * NN;
    const float* crb  = crsum + b * NN;
    uint2* rowEnt = ent + (size_t)gw * CAP;

    int count = 0;
    for (int it = 0; it < 16; it++) {
        const int j0 = it * 128 + lane * 4;
        float4 v  = *(const float4*)(Srow + j0);
        float4 mx = *(const float4*)(cmb  + j0);
        const float vs[4] = {v.x, v.y, v.z, v.w};
        const float ms[4] = {mx.x, mx.y, mx.z, mx.w};
#pragma unroll
        for (int c = 0; c < 4; c++) {
            const float d = vs[c] - ms[c];
            const bool keep = d > -20.0f;
            const unsigned bal = __ballot_sync(0xffffffffu, keep);
            if (keep) {
                const int pos = count + __popc(bal & ((1u << lane) - 1u));
                const float w = __expf(d) * crb[j0 + c];
                rowEnt[pos] = make_uint2((unsigned)(j0 + c), __float_as_uint(w));
            }
            count += __popc(bal);
        }
    }
    if (lane == 0) cnt[gw] = count;
}

// ---------------- sparse output: out[b,n,m] = sum_e w[m,e] * xt[b,e,n] ----------------
// Block per (b, 16-column group). acc[8 n-slices][16 m] in registers; coalesced xt reads;
// 64B-aligned dense writes. Every out element written exactly once.
__global__ __launch_bounds__(256)
void spmm_out(const float* __restrict__ xt, const int* __restrict__ cnt,
              const uint2* __restrict__ ent, float* __restrict__ out)
{
    const int bg = blockIdx.x;            // b*128 + mg
    const int b  = bg >> 7;
    const int m0 = (bg & 127) * 16;
    const int tid = threadIdx.x;
    const float* xtb = xt + (size_t)b * NN * EE;
    float* outb = out + (size_t)b * NN * NN;

    float acc[8][16];
#pragma unroll
    for (int k = 0; k < 8; k++)
#pragma unroll
        for (int j = 0; j < 16; j++) acc[k][j] = 0.0f;

#pragma unroll
    for (int j = 0; j < 16; j++) {
        const int row = b * NN + m0 + j;
        const int c = cnt[row];
        const uint2* re = ent + (size_t)row * CAP;
        for (int idx = 0; idx < c; idx++) {
            const uint2 p = re[idx];
            const float w = __uint_as_float(p.y);
            const float* xr = xtb + (size_t)p.x * NN + tid;
#pragma unroll
            for (int k = 0; k < 8; k++)
                acc[k][j] = fmaf(w, xr[k * 256], acc[k][j]);
        }
    }
#pragma unroll
    for (int k = 0; k < 8; k++) {
        const int n = k * 256 + tid;
        float* dst = outb + (size_t)n * NN + m0;
#pragma unroll
        for (int q = 0; q < 16; q += 4)
            *(float4*)(dst + q) = make_float4(acc[k][q], acc[k][q + 1], acc[k][q + 2], acc[k][q + 3]);
    }
}

// ---------------- launch ----------------
extern "C" void kernel_launch(void* const* d_in, const int* in_sizes, int n_in,
                              void* d_out, int out_size)
{
    const float* X = (const float*)d_in[0];
    const float* W = (const float*)d_in[1];
    // d_in[2] = bias: per-column constant on scores -> cancels in axis-1 softmax.
    // d_in[3] = gamma: scalar constant -> cancels likewise. Both unused.
    float* out = (float*)d_out;

    __nv_bfloat16 *xh, *xl, *wh, *wl, *qh, *ql;
    float *xt, *s, *pm, *ps, *cmax, *csum;
    int *cnt; uint2 *ent;
    cudaGetSymbolAddress((void**)&xh, g_xh);  cudaGetSymbolAddress((void**)&xl, g_xl);
    cudaGetSymbolAddress((void**)&xt, g_xt);
    cudaGetSymbolAddress((void**)&wh, g_wh);  cudaGetSymbolAddress((void**)&wl, g_wl);
    cudaGetSymbolAddress((void**)&qh, g_qh);  cudaGetSymbolAddress((void**)&ql, g_ql);
    cudaGetSymbolAddress((void**)&s,  g_s);
    cudaGetSymbolAddress((void**)&pm, g_pm);  cudaGetSymbolAddress((void**)&ps, g_ps);
    cudaGetSymbolAddress((void**)&cmax, g_cmax);
    cudaGetSymbolAddress((void**)&csum, g_csum);
    cudaGetSymbolAddress((void**)&cnt, g_cnt);
    cudaGetSymbolAddress((void**)&ent, g_ent);

    int dev = 0;  cudaGetDevice(&dev);
    int nsm = 148;
    cudaDeviceGetAttribute(&nsm, cudaDevAttrMultiProcessorCount, dev);

    const int smem = STAGES * STAGE_BYTES + STAT_BYTES;
    cudaFuncSetAttribute((const void*)gemm_mma<96>, cudaFuncAttributeMaxDynamicSharedMemorySize, smem);

    // split inputs, transpose X
    {
        const size_t quads = ((size_t)BATCH * NN * EE + (size_t)EE * EE) / 4;
        split_all<<<(int)(quads / 256), 256>>>(X, W, xh, xl, wh, wl);
    }
    transpose_x<<<dim3(EE / 32, NN / 32, BATCH), 256>>>(X, xt);

    const long long sXE = (long long)NN * EE;
    const long long sNN = (long long)NN * NN;

    // GEMM1: Q = X W^T -> hi/lo bf16. Tiles: gx=16, gy=64.
    gemm_mma<96><<<nsm, 256, smem>>>(xh, xl, wh, wl, 0, 0, 0,
                                     nullptr, qh, ql, 1, 16, 64, 1024,
                                     nullptr, nullptr);

    // GEMM2: S[b] = Q[b] X[b]^T (fp32) + fused per-tile column stats.
    gemm_mma<96><<<nsm, 256, smem>>>(qh, ql, xh, xl, sXE, sXE, sNN,
                                     s, nullptr, nullptr, 0, 16, 8, 1024,
                                     pm, ps);

    // finish column stats; extract sparse attn; sparse output accumulation
    col_finish<<<(BATCH * NN) / 256, 256>>>(pm, ps, cmax, csum);
    extract<<<(BATCH * NN) / 8, 256>>>(s, cmax, csum, cnt, ent);
    spmm_out<<<BATCH * 128, 256>>>(xt, cnt, ent, out);
}

// round 12
// speedup vs baseline: 1.1534x; 1.0083x over previous
#include <cuda_runtime.h>
#include <cuda_bf16.h>
#include <cstdint>

#define BATCH 8
#define NN 2048
#define EE 2048

#define BM 256
#define BN 128
#define STAGES 4
#define STAGE_BYTES 49152       // A: 256x128B (32KB) + B: 128x128B (16KB)
#define STAT_BYTES 4096         // 512 x float2 column-stat scratch
#define CAP 2048                // per-row sparse capacity (cannot overflow)
#define ECH 64                  // spmm entry-chunk per pass

// ---------------- scratch globals (no cudaMalloc allowed) ----------------
__device__ __align__(256) __nv_bfloat16 g_xh[(size_t)BATCH * NN * EE];
__device__ __align__(256) __nv_bfloat16 g_xl[(size_t)BATCH * NN * EE];
__device__ __align__(256) float         g_xt[(size_t)BATCH * NN * EE];   // X^T per batch [e][n]
__device__ __align__(256) __nv_bfloat16 g_wh[(size_t)EE * EE];
__device__ __align__(256) __nv_bfloat16 g_wl[(size_t)EE * EE];
__device__ __align__(256) __nv_bfloat16 g_qh[(size_t)BATCH * NN * EE];
__device__ __align__(256) __nv_bfloat16 g_ql[(size_t)BATCH * NN * EE];
__device__ __align__(256) float         g_s [(size_t)BATCH * NN * NN];
__device__ __align__(256) float         g_pm[BATCH * 8 * NN];
__device__ __align__(256) float         g_ps[BATCH * 8 * NN];
__device__ __align__(256) float         g_cmax[BATCH * NN];
__device__ __align__(256) float         g_csum[BATCH * NN];
__device__ __align__(256) int           g_cnt[BATCH * NN];
__device__ __align__(256) uint2         g_ent[(size_t)BATCH * NN * CAP]; // (e, w bits)

// ---------------- helpers ----------------
__device__ __forceinline__ uint32_t smem_u32(const void* p) {
    uint32_t a;
    asm("{ .reg .u64 t; cvta.to.shared.u64 t, %1; cvt.u32.u64 %0, t; }" : "=r"(a) : "l"(p));
    return a;
}
__device__ __forceinline__ void cp16(uint32_t s, const void* g) {
    asm volatile("cp.async.cg.shared.global [%0], [%1], 16;" :: "r"(s), "l"(g) : "memory");
}
__device__ __forceinline__ void cp_commit() {
    asm volatile("cp.async.commit_group;" ::: "memory");
}
template <int N> __device__ __forceinline__ void cp_wait() {
    asm volatile("cp.async.wait_group %0;" :: "n"(N) : "memory");
}
__device__ __forceinline__ void ldm4(uint32_t* r, uint32_t a) {
    asm volatile("ldmatrix.sync.aligned.m8n8.x4.shared.b16 {%0,%1,%2,%3}, [%4];"
                 : "=r"(r[0]), "=r"(r[1]), "=r"(r[2]), "=r"(r[3]) : "r"(a));
}
__device__ __forceinline__ void mma16816(float* c, const uint32_t* a, uint32_t b0, uint32_t b1) {
    asm volatile(
        "mma.sync.aligned.m16n8k16.row.col.f32.bf16.bf16.f32 "
        "{%0,%1,%2,%3}, {%4,%5,%6,%7}, {%8,%9}, {%0,%1,%2,%3};"
        : "+f"(c[0]), "+f"(c[1]), "+f"(c[2]), "+f"(c[3])
        : "r"(a[0]), "r"(a[1]), "r"(a[2]), "r"(a[3]), "r"(b0), "r"(b1));
}

// ---------------- persistent tensor-core GEMM: C tiles 256x128 = A @ B^T ----------------
// 3-phase bf16 split over K'=96*64: (Ah,Bh) / (Al,Bh) / (Ah,Bl).
// MODE 0: fp32 out (+ fused per-tile column softmax stats when STATS).
// MODE 1: split-store hi/lo bf16 to outH/outL.
template <int MODE, bool STATS>
__global__ __launch_bounds__(256, 1)
void gemm_mma(const void* Ahv, const void* Alv, const void* Bhv, const void* Blv,
              long long aBatch, long long bBatch, long long cBatch,
              float* outF, __nv_bfloat16* outH, __nv_bfloat16* outL,
              int gx, int gy, int nTiles, float* pm, float* ps)
{
    constexpr int NBK = 96;
    extern __shared__ __align__(128) char smem[];
    const uint32_t stg0 = smem_u32(smem);
    const int tid  = threadIdx.x;
    const int lane = tid & 31;
    const int warp = tid >> 5;

    const int lr = tid >> 3;
    const int lc = tid & 7;
    const uint32_t so = (uint32_t)(lr * 128 + ((lc ^ (lr & 7)) << 4));

    const int wm  = warp & 3;
    const int wn  = warp >> 2;
    const int m0w = wm * 64;
    const int n0w = wn * 64;
    const uint32_t aRow  = (uint32_t)(m0w + (lane & 15));
    const uint32_t aBase = aRow * 128;
    const uint32_t aXor  = aRow & 7;
    const uint32_t ac0   = (uint32_t)(lane >> 4);
    const uint32_t bRow  = (uint32_t)(n0w + ((lane >> 4) << 3) + (lane & 7));
    const uint32_t bBase = 32768u + bRow * 128;
    const uint32_t bXor  = (uint32_t)(lane & 7);
    const uint32_t bc0   = (uint32_t)((lane >> 3) & 1);

    float acc[4][8][4] = {};
    uint32_t af[2][4][4], bf[2][4][4];

    const char *gAh, *gAl, *gBh, *gBl;
    auto setLoad = [&](int t) {
        const int bx = t % gx;
        const int r2 = t / gx;
        const int by = r2 % gy;
        const int bz = r2 / gy;
        const size_t aoff = ((size_t)bz * (size_t)aBatch + (size_t)(by * BM + lr) * EE) * 2 + lc * 16;
        const size_t boff = ((size_t)bz * (size_t)bBatch + (size_t)(bx * BN + lr) * EE) * 2 + lc * 16;
        gAh = (const char*)Ahv + aoff;
        gAl = (const char*)Alv + aoff;
        gBh = (const char*)Bhv + boff;
        gBl = (const char*)Blv + boff;
    };

    auto load_chunk = [&](int s, int kbn, int part) {
        const int p = kbn >> 5;
        const char* a = (p == 1) ? gAl : gAh;
        const char* b = (p == 2) ? gBl : gBh;
        const uint32_t koff = (uint32_t)(kbn & 31) * 128;
        const uint32_t dstA = stg0 + (uint32_t)s * STAGE_BYTES + so;
        const uint32_t dstB = dstA + 32768u;
        cp16(dstA + (uint32_t)(part * 2)     * 4096u, a + koff + (size_t)(part * 2)     * 131072);
        cp16(dstA + (uint32_t)(part * 2 + 1) * 4096u, a + koff + (size_t)(part * 2 + 1) * 131072);
        cp16(dstB + (uint32_t)part           * 4096u, b + koff + (size_t)part           * 131072);
        if (part == 3) cp_commit();
    };
    auto ldm_ks = [&](uint32_t sb_, uint32_t ke, int bsel) {
#pragma unroll
        for (int mt = 0; mt < 4; mt++)
            ldm4(af[bsel][mt], sb_ + aBase + mt * 2048u + (((ke * 2 + ac0) ^ aXor) << 4));
#pragma unroll
        for (int np = 0; np < 4; np++)
            ldm4(bf[bsel][np], sb_ + bBase + np * 2048u + (((ke * 2 + bc0) ^ bXor) << 4));
    };

    int t = blockIdx.x;
    if (t >= nTiles) return;
    setLoad(t);
#pragma unroll
    for (int st = 0; st < 3; st++)
        for (int part = 0; part < 4; part++) load_chunk(st, st, part);
    cp_wait<1>();
    __syncthreads();
    ldm_ks(stg0, 0, 0);

    for (;;) {
        const int bx = t % gx;
        const int r2 = t / gx;
        const int row0 = (r2 % gy) * BM;
        const int col0 = bx * BN;
        const int z    = r2 / gy;
        const bool hasNext = (t + (int)gridDim.x) < nTiles;

        for (int kb = 0; kb < NBK; kb++) {
            if (kb == NBK - 3 && hasNext) setLoad(t + (int)gridDim.x);
            const bool doLoad = (kb < NBK - 3) || hasNext;
            const int  kbn    = (kb + 3 < NBK) ? (kb + 3) : (kb + 3 - NBK);
            const uint32_t sb = stg0 + (uint32_t)(kb & 3) * STAGE_BYTES;
#pragma unroll
            for (int ks = 0; ks < 4; ks++) {
                if (doLoad) load_chunk((kb + 3) & 3, kbn, ks);
                const int cur = ks & 1;
                if (ks < 3)
                    ldm_ks(sb, (uint32_t)ks + 1, cur ^ 1);
                else if (kb + 1 < NBK)
                    ldm_ks(stg0 + (uint32_t)((kb + 1) & 3) * STAGE_BYTES, 0, cur ^ 1);
#pragma unroll
                for (int mt = 0; mt < 4; mt++)
#pragma unroll
                    for (int np = 0; np < 4; np++) {
                        mma16816(acc[mt][np * 2],     af[cur][mt], bf[cur][np][0], bf[cur][np][1]);
                        mma16816(acc[mt][np * 2 + 1], af[cur][mt], bf[cur][np][2], bf[cur][np][3]);
                    }
            }
            if (kb + 1 < NBK) {
                if (doLoad) cp_wait<1>(); else cp_wait<0>();
                __syncthreads();
            }
        }
        if (hasNext) cp_wait<1>(); else cp_wait<0>();
        __syncthreads();
        if (hasNext) ldm_ks(stg0, 0, 0);

        // -------- epilogue --------
        const int g  = lane >> 2;
        const int tg = lane & 3;
        if (MODE == 0) {
            float* base = outF + (size_t)z * (size_t)cBatch;
#pragma unroll
            for (int mt = 0; mt < 4; mt++) {
                const int rg = row0 + m0w + mt * 16 + g;
#pragma unroll
                for (int nt = 0; nt < 8; nt++) {
                    const int cg = col0 + n0w + nt * 8 + 2 * tg;
                    *(float2*)(base + (size_t)rg * 2048 + cg)       = make_float2(acc[mt][nt][0], acc[mt][nt][1]);
                    *(float2*)(base + (size_t)(rg + 8) * 2048 + cg) = make_float2(acc[mt][nt][2], acc[mt][nt][3]);
                }
            }
            if (STATS) {
                float2* sst = (float2*)(smem + STAGES * STAGE_BYTES);
#pragma unroll
                for (int nt = 0; nt < 8; nt++) {
#pragma unroll
                    for (int p = 0; p < 2; p++) {
                        float m = acc[0][nt][p];
#pragma unroll
                        for (int mt = 0; mt < 4; mt++) {
                            m = fmaxf(m, acc[mt][nt][p]);
                            m = fmaxf(m, acc[mt][nt][2 + p]);
                        }
                        float s = 0.0f;
#pragma unroll
                        for (int mt = 0; mt < 4; mt++) {
                            s += __expf(acc[mt][nt][p]     - m);
                            s += __expf(acc[mt][nt][2 + p] - m);
                        }
#pragma unroll
                        for (int off = 4; off < 32; off <<= 1) {
                            float om = __shfl_xor_sync(0xffffffffu, m, off);
                            float os = __shfl_xor_sync(0xffffffffu, s, off);
                            if (om > m) { s = s * __expf(m - om) + os; m = om; }
                            else        { s += os * __expf(om - m); }
                        }
                        if (lane < 4) {
                            const int colLocal = n0w + nt * 8 + lane * 2 + p;
                            sst[colLocal * 4 + wm] = make_float2(m, s);
                        }
                    }
                }
                __syncthreads();
                if (tid < 128) {
                    float2 a0 = sst[tid * 4 + 0];
                    float2 a1 = sst[tid * 4 + 1];
                    float2 a2 = sst[tid * 4 + 2];
                    float2 a3 = sst[tid * 4 + 3];
                    float M = fmaxf(fmaxf(a0.x, a1.x), fmaxf(a2.x, a3.x));
                    float S = a0.y * __expf(a0.x - M) + a1.y * __expf(a1.x - M)
                            + a2.y * __expf(a2.x - M) + a3.y * __expf(a3.x - M);
                    const size_t o = ((size_t)z * (size_t)gy + (size_t)(row0 / BM)) * NN
                                   + (size_t)(col0 + tid);
                    pm[o] = M;
                    ps[o] = S;
                }
            }
        } else {
#pragma unroll
            for (int mt = 0; mt < 4; mt++) {
                const int rg = row0 + m0w + mt * 16 + g;
#pragma unroll
                for (int nt = 0; nt < 8; nt++) {
                    const int cg = col0 + n0w + nt * 8 + 2 * tg;
                    float v[4] = {acc[mt][nt][0], acc[mt][nt][1], acc[mt][nt][2], acc[mt][nt][3]};
                    __nv_bfloat16 h0 = __float2bfloat16(v[0]), h1 = __float2bfloat16(v[1]);
                    __nv_bfloat16 h2 = __float2bfloat16(v[2]), h3 = __float2bfloat16(v[3]);
                    __nv_bfloat16 l0 = __float2bfloat16(v[0] - __bfloat162float(h0));
                    __nv_bfloat16 l1 = __float2bfloat16(v[1] - __bfloat162float(h1));
                    __nv_bfloat16 l2 = __float2bfloat16(v[2] - __bfloat162float(h2));
                    __nv_bfloat16 l3 = __float2bfloat16(v[3] - __bfloat162float(h3));
                    *(__nv_bfloat162*)(outH + (size_t)rg * 2048 + cg)       = __nv_bfloat162(h0, h1);
                    *(__nv_bfloat162*)(outL + (size_t)rg * 2048 + cg)       = __nv_bfloat162(l0, l1);
                    *(__nv_bfloat162*)(outH + (size_t)(rg + 8) * 2048 + cg) = __nv_bfloat162(h2, h3);
                    *(__nv_bfloat162*)(outL + (size_t)(rg + 8) * 2048 + cg) = __nv_bfloat162(l2, l3);
                }
            }
        }
        if (!hasNext) break;
#pragma unroll
        for (int mt = 0; mt < 4; mt++)
#pragma unroll
            for (int nt = 0; nt < 8; nt++)
#pragma unroll
                for (int q = 0; q < 4; q++) acc[mt][nt][q] = 0.0f;
        t += (int)gridDim.x;
    }
}

// ---------------- fused prep: X -> (bf16 hi/lo + fp32 transpose), W -> bf16 hi/lo ----------------
// grid (64, 64, 9): z<8 = batch slice of X (read once), z==8 = W elementwise.
__global__ __launch_bounds__(256)
void prep(const float* __restrict__ X, const float* __restrict__ W,
          __nv_bfloat16* __restrict__ xh, __nv_bfloat16* __restrict__ xl,
          float* __restrict__ xt,
          __nv_bfloat16* __restrict__ wh, __nv_bfloat16* __restrict__ wl)
{
    const int c  = threadIdx.x & 31;
    const int r0 = threadIdx.x >> 5;
    const int e0 = blockIdx.x * 32;
    const int n0 = blockIdx.y * 32;
    if (blockIdx.z == 8) {
#pragma unroll
        for (int k = 0; k < 4; k++) {
            const int r = r0 + k * 8;
            const size_t i = (size_t)(n0 + r) * EE + e0 + c;
            const float v = W[i];
            const __nv_bfloat16 h = __float2bfloat16(v);
            wh[i] = h;
            wl[i] = __float2bfloat16(v - __bfloat162float(h));
        }
        return;
    }
    __shared__ float tile[32][33];
    const int b = blockIdx.z;
    const float* Xb  = X  + (size_t)b * NN * EE;
    float*       xtb = xt + (size_t)b * NN * EE;
#pragma unroll
    for (int k = 0; k < 4; k++) {
        const int r = r0 + k * 8;
        const size_t i = (size_t)(n0 + r) * EE + e0 + c;
        const float v = Xb[i];
        tile[r][c] = v;
        const __nv_bfloat16 h = __float2bfloat16(v);
        xh[(size_t)b * NN * EE + i] = h;
        xl[(size_t)b * NN * EE + i] = __float2bfloat16(v - __bfloat162float(h));
    }
    __syncthreads();
#pragma unroll
    for (int k = 0; k < 4; k++) {
        const int r = r0 + k * 8;
        xtb[(size_t)(e0 + r) * NN + n0 + c] = tile[c][r];
    }
}

// ---------------- combine per-tile column stats -> cmax, 1/sum ----------------
__global__ void col_finish(const float* __restrict__ pm, const float* __restrict__ ps,
                           float* __restrict__ cmax, float* __restrict__ crsum)
{
    const int i = blockIdx.x * blockDim.x + threadIdx.x;
    const int b = i >> 11, col = i & 2047;
    const float* pmb = pm + (size_t)b * 8 * NN + col;
    const float* psb = ps + (size_t)b * 8 * NN + col;
    float M = pmb[0], S = psb[0];
#pragma unroll
    for (int t2 = 1; t2 < 8; t2++) {
        const float m = pmb[(size_t)t2 * NN], s = psb[(size_t)t2 * NN];
        if (m > M) { S = S * __expf(M - m) + s; M = m; }
        else       { S += s * __expf(m - M); }
    }
    cmax[i]  = M;
    crsum[i] = 1.0f / S;
}

// ---------------- sparse extraction: warp per attn-row (b,m) ----------------
// Keep entries with S-cmax > -20 (dropped mass < 2048*e^-20 ~ 4e-6: always safe).
__global__ __launch_bounds__(256)
void extract(const float* __restrict__ S,
             const float* __restrict__ cmax, const float* __restrict__ crsum,
             int* __restrict__ cnt, uint2* __restrict__ ent)
{
    const int gw   = (int)((blockIdx.x * blockDim.x + threadIdx.x) >> 5);
    const int lane = threadIdx.x & 31;
    const int b = gw >> 11;
    const float* Srow = S + (size_t)gw * NN;
    const float* cmb  = cmax  + b * NN;
    const float* crb  = crsum + b * NN;
    uint2* rowEnt = ent + (size_t)gw * CAP;

    int count = 0;
    for (int it = 0; it < 16; it++) {
        const int j0 = it * 128 + lane * 4;
        float4 v  = *(const float4*)(Srow + j0);
        float4 mx = *(const float4*)(cmb  + j0);
        const float vs[4] = {v.x, v.y, v.z, v.w};
        const float ms[4] = {mx.x, mx.y, mx.z, mx.w};
#pragma unroll
        for (int c = 0; c < 4; c++) {
            const float d = vs[c] - ms[c];
            const bool keep = d > -20.0f;
            const unsigned bal = __ballot_sync(0xffffffffu, keep);
            if (keep) {
                const int pos = count + __popc(bal & ((1u << lane) - 1u));
                const float w = __expf(d) * crb[j0 + c];
                rowEnt[pos] = make_uint2((unsigned)(j0 + c), __float_as_uint(w));
            }
            count += __popc(bal);
        }
    }
    if (lane == 0) cnt[gw] = count;
}

// ---------------- sparse output: out[b,n,m] = sum_e w[m,e] * xt[b,e,n] ----------------
// Block per (n-half, m-group of 32, b). Entries staged via smem in ECH-passes,
// accumulate in regs (acc[4 n][32 m]), write via smem transpose: 128B lines.
__global__ __launch_bounds__(256)
void spmm_out(const float* __restrict__ xt, const int* __restrict__ cnt,
              const uint2* __restrict__ ent, float* __restrict__ out)
{
    extern __shared__ __align__(16) char dsm[];
    uint2 (*sent)[ECH] = (uint2 (*)[ECH])dsm;          // [32][ECH]
    int*   scnt        = (int*)(dsm + 32 * ECH * 8);   // [32]
    float (*buf)[36]   = (float (*)[36])dsm;           // write staging (reuses dsm)

    const int nh = blockIdx.x;            // 0..1
    const int mg = blockIdx.y;            // 0..63
    const int b  = blockIdx.z;            // 0..7
    const int m0 = mg * 32;
    const int nbase = nh * 1024;
    const int tid = threadIdx.x;
    const float* xtb = xt + (size_t)b * NN * EE;
    float* outb = out + (size_t)b * NN * NN;

    // counts + max count
    if (tid < 32) scnt[tid] = cnt[b * NN + m0 + tid];
    __syncthreads();
    int maxc = 0;
#pragma unroll
    for (int j = 0; j < 32; j++) maxc = max(maxc, scnt[j]);

    float acc[4][32];
#pragma unroll
    for (int k = 0; k < 4; k++)
#pragma unroll
        for (int j = 0; j < 32; j++) acc[k][j] = 0.0f;

    const int passes = (maxc + ECH - 1) / ECH;
    for (int pass = 0; pass < passes; pass++) {
        // stage entries: thread -> (row = tid>>3, slots (tid&7) + 8s)
        const int srow = tid >> 3;
        const int base = pass * ECH;
        const int avail = min(scnt[srow] - base, ECH);
#pragma unroll
        for (int s2 = 0; s2 < ECH / 8; s2++) {
            const int slot = (tid & 7) + s2 * 8;
            if (slot < avail)
                sent[srow][slot] = ent[(size_t)(b * NN + m0 + srow) * CAP + base + slot];
        }
        __syncthreads();
#pragma unroll
        for (int j = 0; j < 32; j++) {
            const int cj = min(scnt[j] - base, ECH);
            for (int idx = 0; idx < cj; idx++) {
                const uint2 p = sent[j][idx];
                const float w = __uint_as_float(p.y);
                const float* xr = xtb + (size_t)p.x * NN + nbase + tid;
                acc[0][j] = fmaf(w, xr[0],   acc[0][j]);
                acc[1][j] = fmaf(w, xr[256], acc[1][j]);
                acc[2][j] = fmaf(w, xr[512], acc[2][j]);
                acc[3][j] = fmaf(w, xr[768], acc[3][j]);
            }
        }
        __syncthreads();
    }

    // write: per k, stage [256 n][32 m] in smem, then 128B-coalesced stores
#pragma unroll
    for (int k = 0; k < 4; k++) {
        __syncthreads();
#pragma unroll
        for (int j = 0; j < 32; j++) buf[tid][j] = acc[k][j];
        __syncthreads();
#pragma unroll
        for (int s2 = 0; s2 < 8; s2++) {
            const int lin = s2 * 256 + tid;
            const int r   = lin >> 3;
            const int c4  = (lin & 7) * 4;
            const int n   = nbase + k * 256 + r;
            *(float4*)(outb + (size_t)n * NN + m0 + c4) =
                make_float4(buf[r][c4], buf[r][c4 + 1], buf[r][c4 + 2], buf[r][c4 + 3]);
        }
    }
}

// ---------------- launch ----------------
extern "C" void kernel_launch(void* const* d_in, const int* in_sizes, int n_in,
                              void* d_out, int out_size)
{
    const float* X = (const float*)d_in[0];
    const float* W = (const float*)d_in[1];
    // d_in[2] = bias: per-column constant on scores -> cancels in axis-1 softmax.
    // d_in[3] = gamma: scalar constant -> cancels likewise. Both unused.
    float* out = (float*)d_out;

    __nv_bfloat16 *xh, *xl, *wh, *wl, *qh, *ql;
    float *xt, *s, *pm, *ps, *cmax, *csum;
    int *cnt; uint2 *ent;
    cudaGetSymbolAddress((void**)&xh, g_xh);  cudaGetSymbolAddress((void**)&xl, g_xl);
    cudaGetSymbolAddress((void**)&xt, g_xt);
    cudaGetSymbolAddress((void**)&wh, g_wh);  cudaGetSymbolAddress((void**)&wl, g_wl);
    cudaGetSymbolAddress((void**)&qh, g_qh);  cudaGetSymbolAddress((void**)&ql, g_ql);
    cudaGetSymbolAddress((void**)&s,  g_s);
    cudaGetSymbolAddress((void**)&pm, g_pm);  cudaGetSymbolAddress((void**)&ps, g_ps);
    cudaGetSymbolAddress((void**)&cmax, g_cmax);
    cudaGetSymbolAddress((void**)&csum, g_csum);
    cudaGetSymbolAddress((void**)&cnt, g_cnt);
    cudaGetSymbolAddress((void**)&ent, g_ent);

    int dev = 0;  cudaGetDevice(&dev);
    int nsm = 148;
    cudaDeviceGetAttribute(&nsm, cudaDevAttrMultiProcessorCount, dev);

    const int smemG = STAGES * STAGE_BYTES + STAT_BYTES;
    cudaFuncSetAttribute((const void*)gemm_mma<1, false>, cudaFuncAttributeMaxDynamicSharedMemorySize, smemG);
    cudaFuncSetAttribute((const void*)gemm_mma<0, true>,  cudaFuncAttributeMaxDynamicSharedMemorySize, smemG);

    // fused prep: X -> xh/xl/xt (one read), W -> wh/wl
    prep<<<dim3(64, 64, 9), 256>>>(X, W, xh, xl, xt, wh, wl);

    const long long sXE = (long long)NN * EE;
    const long long sNN = (long long)NN * NN;

    // GEMM1: Q = X W^T -> hi/lo bf16. Tiles: gx=16, gy=64.
    gemm_mma<1, false><<<nsm, 256, smemG>>>(xh, xl, wh, wl, 0, 0, 0,
                                            nullptr, qh, ql, 16, 64, 1024,
                                            nullptr, nullptr);

    // GEMM2: S[b] = Q[b] X[b]^T (fp32) + fused per-tile column stats.
    gemm_mma<0, true><<<nsm, 256, smemG>>>(qh, ql, xh, xl, sXE, sXE, sNN,
                                           s, nullptr, nullptr, 16, 8, 1024,
                                           pm, ps);

    // finish column stats; extract sparse attn; sparse output accumulation
    col_finish<<<(BATCH * NN) / 256, 256>>>(pm, ps, cmax, csum);
    extract<<<(BATCH * NN) / 8, 256>>>(s, cmax, csum, cnt, ent);
    {
        const int smemS = 256 * 36 * 4;   // 36864 B (>= 32*ECH*8 + 128)
        spmm_out<<<dim3(2, 64, BATCH), 256, smemS>>>(xt, cnt, ent, out);
    }
}

// round 13
// speedup vs baseline: 1.1913x; 1.0329x over previous
#include <cuda_runtime.h>
#include <cuda_bf16.h>
#include <cuda_fp16.h>
#include <cstdint>

#define BATCH 8
#define NN 2048
#define EE 2048

#define BM 256
#define BN 128
#define STAGES 4
#define STAGE_BYTES 49152       // A: 256x128B (32KB) + B: 128x128B (16KB)
#define STAT_BYTES 4096         // 512 x float2 column-stat scratch
#define CAP 2048                // per-row sparse capacity (cannot overflow)
#define ECH 64                  // spmm entry-chunk per pass
#define MG  16                  // spmm m-group

// ---------------- scratch globals (no cudaMalloc allowed) ----------------
__device__ __align__(256) __nv_bfloat16 g_xh[(size_t)BATCH * NN * EE];
__device__ __align__(256) __nv_bfloat16 g_xl[(size_t)BATCH * NN * EE];
__device__ __align__(256) __half        g_xt[(size_t)BATCH * NN * EE];   // X^T per batch [e][n], fp16
__device__ __align__(256) __nv_bfloat16 g_wh[(size_t)EE * EE];
__device__ __align__(256) __nv_bfloat16 g_wl[(size_t)EE * EE];
__device__ __align__(256) __nv_bfloat16 g_qh[(size_t)BATCH * NN * EE];
__device__ __align__(256) __nv_bfloat16 g_ql[(size_t)BATCH * NN * EE];
__device__ __align__(256) float         g_s [(size_t)BATCH * NN * NN];
__device__ __align__(256) float         g_pm[BATCH * 8 * NN];
__device__ __align__(256) float         g_ps[BATCH * 8 * NN];
__device__ __align__(256) float         g_cmax[BATCH * NN];
__device__ __align__(256) float         g_csum[BATCH * NN];
__device__ __align__(256) int           g_cnt[BATCH * NN];
__device__ __align__(256) uint2         g_ent[(size_t)BATCH * NN * CAP]; // (e, w bits)

// ---------------- helpers ----------------
__device__ __forceinline__ uint32_t smem_u32(const void* p) {
    uint32_t a;
    asm("{ .reg .u64 t; cvta.to.shared.u64 t, %1; cvt.u32.u64 %0, t; }" : "=r"(a) : "l"(p));
    return a;
}
__device__ __forceinline__ void cp16(uint32_t s, const void* g) {
    asm volatile("cp.async.cg.shared.global [%0], [%1], 16;" :: "r"(s), "l"(g) : "memory");
}
__device__ __forceinline__ void cp_commit() {
    asm volatile("cp.async.commit_group;" ::: "memory");
}
template <int N> __device__ __forceinline__ void cp_wait() {
    asm volatile("cp.async.wait_group %0;" :: "n"(N) : "memory");
}
__device__ __forceinline__ void ldm4(uint32_t* r, uint32_t a) {
    asm volatile("ldmatrix.sync.aligned.m8n8.x4.shared.b16 {%0,%1,%2,%3}, [%4];"
                 : "=r"(r[0]), "=r"(r[1]), "=r"(r[2]), "=r"(r[3]) : "r"(a));
}
__device__ __forceinline__ void mma16816(float* c, const uint32_t* a, uint32_t b0, uint32_t b1) {
    asm volatile(
        "mma.sync.aligned.m16n8k16.row.col.f32.bf16.bf16.f32 "
        "{%0,%1,%2,%3}, {%4,%5,%6,%7}, {%8,%9}, {%0,%1,%2,%3};"
        : "+f"(c[0]), "+f"(c[1]), "+f"(c[2]), "+f"(c[3])
        : "r"(a[0]), "r"(a[1]), "r"(a[2]), "r"(a[3]), "r"(b0), "r"(b1));
}

// ---------------- persistent tensor-core GEMM: C tiles 256x128 = A @ B^T ----------------
// 3-phase bf16 split over K'=96*64: (Ah,Bh) / (Al,Bh) / (Ah,Bl).
// MODE 0: fp32 out (+ fused per-tile column softmax stats when STATS).
// MODE 1: split-store hi/lo bf16 to outH/outL.
template <int MODE, bool STATS>
__global__ __launch_bounds__(256, 1)
void gemm_mma(const void* Ahv, const void* Alv, const void* Bhv, const void* Blv,
              long long aBatch, long long bBatch, long long cBatch,
              float* outF, __nv_bfloat16* outH, __nv_bfloat16* outL,
              int gx, int gy, int nTiles, float* pm, float* ps)
{
    constexpr int NBK = 96;
    extern __shared__ __align__(128) char smem[];
    const uint32_t stg0 = smem_u32(smem);
    const int tid  = threadIdx.x;
    const int lane = tid & 31;
    const int warp = tid >> 5;

    const int lr = tid >> 3;
    const int lc = tid & 7;
    const uint32_t so = (uint32_t)(lr * 128 + ((lc ^ (lr & 7)) << 4));

    const int wm  = warp & 3;
    const int wn  = warp >> 2;
    const int m0w = wm * 64;
    const int n0w = wn * 64;
    const uint32_t aRow  = (uint32_t)(m0w + (lane & 15));
    const uint32_t aBase = aRow * 128;
    const uint32_t aXor  = aRow & 7;
    const uint32_t ac0   = (uint32_t)(lane >> 4);
    const uint32_t bRow  = (uint32_t)(n0w + ((lane >> 4) << 3) + (lane & 7));
    const uint32_t bBase = 32768u + bRow * 128;
    const uint32_t bXor  = (uint32_t)(lane & 7);
    const uint32_t bc0   = (uint32_t)((lane >> 3) & 1);

    float acc[4][8][4] = {};
    uint32_t af[2][4][4], bf[2][4][4];

    const char *gAh, *gAl, *gBh, *gBl;
    auto setLoad = [&](int t) {
        const int bx = t % gx;
        const int r2 = t / gx;
        const int by = r2 % gy;
        const int bz = r2 / gy;
        const size_t aoff = ((size_t)bz * (size_t)aBatch + (size_t)(by * BM + lr) * EE) * 2 + lc * 16;
        const size_t boff = ((size_t)bz * (size_t)bBatch + (size_t)(bx * BN + lr) * EE) * 2 + lc * 16;
        gAh = (const char*)Ahv + aoff;
        gAl = (const char*)Alv + aoff;
        gBh = (const char*)Bhv + boff;
        gBl = (const char*)Blv + boff;
    };

    auto load_chunk = [&](int s, int kbn, int part) {
        const int p = kbn >> 5;
        const char* a = (p == 1) ? gAl : gAh;
        const char* b = (p == 2) ? gBl : gBh;
        const uint32_t koff = (uint32_t)(kbn & 31) * 128;
        const uint32_t dstA = stg0 + (uint32_t)s * STAGE_BYTES + so;
        const uint32_t dstB = dstA + 32768u;
        cp16(dstA + (uint32_t)(part * 2)     * 4096u, a + koff + (size_t)(part * 2)     * 131072);
        cp16(dstA + (uint32_t)(part * 2 + 1) * 4096u, a + koff + (size_t)(part * 2 + 1) * 131072);
        cp16(dstB + (uint32_t)part           * 4096u, b + koff + (size_t)part           * 131072);
        if (part == 3) cp_commit();
    };
    auto ldm_ks = [&](uint32_t sb_, uint32_t ke, int bsel) {
#pragma unroll
        for (int mt = 0; mt < 4; mt++)
            ldm4(af[bsel][mt], sb_ + aBase + mt * 2048u + (((ke * 2 + ac0) ^ aXor) << 4));
#pragma unroll
        for (int np = 0; np < 4; np++)
            ldm4(bf[bsel][np], sb_ + bBase + np * 2048u + (((ke * 2 + bc0) ^ bXor) << 4));
    };

    int t = blockIdx.x;
    if (t >= nTiles) return;
    setLoad(t);
#pragma unroll
    for (int st = 0; st < 3; st++)
        for (int part = 0; part < 4; part++) load_chunk(st, st, part);
    cp_wait<1>();
    __syncthreads();
    ldm_ks(stg0, 0, 0);

    for (;;) {
        const int bx = t % gx;
        const int r2 = t / gx;
        const int row0 = (r2 % gy) * BM;
        const int col0 = bx * BN;
        const int z    = r2 / gy;
        const bool hasNext = (t + (int)gridDim.x) < nTiles;

        for (int kb = 0; kb < NBK; kb++) {
            if (kb == NBK - 3 && hasNext) setLoad(t + (int)gridDim.x);
            const bool doLoad = (kb < NBK - 3) || hasNext;
            const int  kbn    = (kb + 3 < NBK) ? (kb + 3) : (kb + 3 - NBK);
            const uint32_t sb = stg0 + (uint32_t)(kb & 3) * STAGE_BYTES;
#pragma unroll
            for (int ks = 0; ks < 4; ks++) {
                if (doLoad) load_chunk((kb + 3) & 3, kbn, ks);
                const int cur = ks & 1;
                if (ks < 3)
                    ldm_ks(sb, (uint32_t)ks + 1, cur ^ 1);
                else if (kb + 1 < NBK)
                    ldm_ks(stg0 + (uint32_t)((kb + 1) & 3) * STAGE_BYTES, 0, cur ^ 1);
#pragma unroll
                for (int mt = 0; mt < 4; mt++)
#pragma unroll
                    for (int np = 0; np < 4; np++) {
                        mma16816(acc[mt][np * 2],     af[cur][mt], bf[cur][np][0], bf[cur][np][1]);
                        mma16816(acc[mt][np * 2 + 1], af[cur][mt], bf[cur][np][2], bf[cur][np][3]);
                    }
            }
            if (kb + 1 < NBK) {
                if (doLoad) cp_wait<1>(); else cp_wait<0>();
                __syncthreads();
            }
        }
        if (hasNext) cp_wait<1>(); else cp_wait<0>();
        __syncthreads();
        if (hasNext) ldm_ks(stg0, 0, 0);

        // -------- epilogue --------
        const int g  = lane >> 2;
        const int tg = lane & 3;
        if (MODE == 0) {
            float* base = outF + (size_t)z * (size_t)cBatch;
#pragma unroll
            for (int mt = 0; mt < 4; mt++) {
                const int rg = row0 + m0w + mt * 16 + g;
#pragma unroll
                for (int nt = 0; nt < 8; nt++) {
                    const int cg = col0 + n0w + nt * 8 + 2 * tg;
                    *(float2*)(base + (size_t)rg * 2048 + cg)       = make_float2(acc[mt][nt][0], acc[mt][nt][1]);
                    *(float2*)(base + (size_t)(rg + 8) * 2048 + cg) = make_float2(acc[mt][nt][2], acc[mt][nt][3]);
                }
            }
            if (STATS) {
                float2* sst = (float2*)(smem + STAGES * STAGE_BYTES);
#pragma unroll
                for (int nt = 0; nt < 8; nt++) {
#pragma unroll
                    for (int p = 0; p < 2; p++) {
                        float m = acc[0][nt][p];
#pragma unroll
                        for (int mt = 0; mt < 4; mt++) {
                            m = fmaxf(m, acc[mt][nt][p]);
                            m = fmaxf(m, acc[mt][nt][2 + p]);
                        }
                        float s = 0.0f;
#pragma unroll
                        for (int mt = 0; mt < 4; mt++) {
                            s += __expf(acc[mt][nt][p]     - m);
                            s += __expf(acc[mt][nt][2 + p] - m);
                        }
#pragma unroll
                        for (int off = 4; off < 32; off <<= 1) {
                            float om = __shfl_xor_sync(0xffffffffu, m, off);
                            float os = __shfl_xor_sync(0xffffffffu, s, off);
                            if (om > m) { s = s * __expf(m - om) + os; m = om; }
                            else        { s += os * __expf(om - m); }
                        }
                        if (lane < 4) {
                            const int colLocal = n0w + nt * 8 + lane * 2 + p;
                            sst[colLocal * 4 + wm] = make_float2(m, s);
                        }
                    }
                }
                __syncthreads();
                if (tid < 128) {
                    float2 a0 = sst[tid * 4 + 0];
                    float2 a1 = sst[tid * 4 + 1];
                    float2 a2 = sst[tid * 4 + 2];
                    float2 a3 = sst[tid * 4 + 3];
                    float M = fmaxf(fmaxf(a0.x, a1.x), fmaxf(a2.x, a3.x));
                    float S = a0.y * __expf(a0.x - M) + a1.y * __expf(a1.x - M)
                            + a2.y * __expf(a2.x - M) + a3.y * __expf(a3.x - M);
                    const size_t o = ((size_t)z * (size_t)gy + (size_t)(row0 / BM)) * NN
                                   + (size_t)(col0 + tid);
                    pm[o] = M;
                    ps[o] = S;
                }
            }
        } else {
#pragma unroll
            for (int mt = 0; mt < 4; mt++) {
                const int rg = row0 + m0w + mt * 16 + g;
#pragma unroll
                for (int nt = 0; nt < 8; nt++) {
                    const int cg = col0 + n0w + nt * 8 + 2 * tg;
                    float v[4] = {acc[mt][nt][0], acc[mt][nt][1], acc[mt][nt][2], acc[mt][nt][3]};
                    __nv_bfloat16 h0 = __float2bfloat16(v[0]), h1 = __float2bfloat16(v[1]);
                    __nv_bfloat16 h2 = __float2bfloat16(v[2]), h3 = __float2bfloat16(v[3]);
                    __nv_bfloat16 l0 = __float2bfloat16(v[0] - __bfloat162float(h0));
                    __nv_bfloat16 l1 = __float2bfloat16(v[1] - __bfloat162float(h1));
                    __nv_bfloat16 l2 = __float2bfloat16(v[2] - __bfloat162float(h2));
                    __nv_bfloat16 l3 = __float2bfloat16(v[3] - __bfloat162float(h3));
                    *(__nv_bfloat162*)(outH + (size_t)rg * 2048 + cg)       = __nv_bfloat162(h0, h1);
                    *(__nv_bfloat162*)(outL + (size_t)rg * 2048 + cg)       = __nv_bfloat162(l0, l1);
                    *(__nv_bfloat162*)(outH + (size_t)(rg + 8) * 2048 + cg) = __nv_bfloat162(h2, h3);
                    *(__nv_bfloat162*)(outL + (size_t)(rg + 8) * 2048 + cg) = __nv_bfloat162(l2, l3);
                }
            }
        }
        if (!hasNext) break;
#pragma unroll
        for (int mt = 0; mt < 4; mt++)
#pragma unroll
            for (int nt = 0; nt < 8; nt++)
#pragma unroll
                for (int q = 0; q < 4; q++) acc[mt][nt][q] = 0.0f;
        t += (int)gridDim.x;
    }
}

// ---------------- fused prep: X -> (bf16 hi/lo + fp16 transpose), W -> bf16 hi/lo ----------------
__global__ __launch_bounds__(256)
void prep(const float* __restrict__ X, const float* __restrict__ W,
          __nv_bfloat16* __restrict__ xh, __nv_bfloat16* __restrict__ xl,
          __half* __restrict__ xt,
          __nv_bfloat16* __restrict__ wh, __nv_bfloat16* __restrict__ wl)
{
    const int c  = threadIdx.x & 31;
    const int r0 = threadIdx.x >> 5;
    const int e0 = blockIdx.x * 32;
    const int n0 = blockIdx.y * 32;
    if (blockIdx.z == 8) {
#pragma unroll
        for (int k = 0; k < 4; k++) {
            const int r = r0 + k * 8;
            const size_t i = (size_t)(n0 + r) * EE + e0 + c;
            const float v = W[i];
            const __nv_bfloat16 h = __float2bfloat16(v);
            wh[i] = h;
            wl[i] = __float2bfloat16(v - __bfloat162float(h));
        }
        return;
    }
    __shared__ float tile[32][33];
    const int b = blockIdx.z;
    const float* Xb  = X  + (size_t)b * NN * EE;
    __half*      xtb = xt + (size_t)b * NN * EE;
#pragma unroll
    for (int k = 0; k < 4; k++) {
        const int r = r0 + k * 8;
        const size_t i = (size_t)(n0 + r) * EE + e0 + c;
        const float v = Xb[i];
        tile[r][c] = v;
        const __nv_bfloat16 h = __float2bfloat16(v);
        xh[(size_t)b * NN * EE + i] = h;
        xl[(size_t)b * NN * EE + i] = __float2bfloat16(v - __bfloat162float(h));
    }
    __syncthreads();
#pragma unroll
    for (int k = 0; k < 4; k++) {
        const int r = r0 + k * 8;
        xtb[(size_t)(e0 + r) * NN + n0 + c] = __float2half(tile[c][r]);
    }
}

// ---------------- combine per-tile column stats -> cmax, 1/sum ----------------
__global__ void col_finish(const float* __restrict__ pm, const float* __restrict__ ps,
                           float* __restrict__ cmax, float* __restrict__ crsum)
{
    const int i = blockIdx.x * blockDim.x + threadIdx.x;
    const int b = i >> 11, col = i & 2047;
    const float* pmb = pm + (size_t)b * 8 * NN + col;
    const float* psb = ps + (size_t)b * 8 * NN + col;
    float M = pmb[0], S = psb[0];
#pragma unroll
    for (int t2 = 1; t2 < 8; t2++) {
        const float m = pmb[(size_t)t2 * NN], s = psb[(size_t)t2 * NN];
        if (m > M) { S = S * __expf(M - m) + s; M = m; }
        else       { S += s * __expf(m - M); }
    }
    cmax[i]  = M;
    crsum[i] = 1.0f / S;
}

// ---------------- sparse extraction: warp per attn-row (b,m) ----------------
// Keep entries with S-cmax > -20 (dropped mass < 2048*e^-20 ~ 4e-6: always safe).
__global__ __launch_bounds__(256)
void extract(const float* __restrict__ S,
             const float* __restrict__ cmax, const float* __restrict__ crsum,
             int* __restrict__ cnt, uint2* __restrict__ ent)
{
    const int gw   = (int)((blockIdx.x * blockDim.x + threadIdx.x) >> 5);
    const int lane = threadIdx.x & 31;
    const int b = gw >> 11;
    const float* Srow = S + (size_t)gw * NN;
    const float* cmb  = cmax  + b * NN;
    const float* crb  = crsum + b * NN;
    uint2* rowEnt = ent + (size_t)gw * CAP;

    int count = 0;
    for (int it = 0; it < 16; it++) {
        const int j0 = it * 128 + lane * 4;
        float4 v  = *(const float4*)(Srow + j0);
        float4 mx = *(const float4*)(cmb  + j0);
        const float vs[4] = {v.x, v.y, v.z, v.w};
        const float ms[4] = {mx.x, mx.y, mx.z, mx.w};
#pragma unroll
        for (int c = 0; c < 4; c++) {
            const float d = vs[c] - ms[c];
            const bool keep = d > -20.0f;
            const unsigned bal = __ballot_sync(0xffffffffu, keep);
            if (keep) {
                const int pos = count + __popc(bal & ((1u << lane) - 1u));
                const float w = __expf(d) * crb[j0 + c];
                rowEnt[pos] = make_uint2((unsigned)(j0 + c), __float_as_uint(w));
            }
            count += __popc(bal);
        }
    }
    if (lane == 0) cnt[gw] = count;
}

// ---------------- sparse output: out[b,n,m] = sum_e w[m,e] * xt[b,e,n] ----------------
// Block per (m-group of 16, b), FULL n range: each entry's xt row (fp16, 4KB)
// is read exactly once per block. Entries staged via smem; coalesced writes.
__global__ __launch_bounds__(256)
void spmm_out(const __half* __restrict__ xt, const int* __restrict__ cnt,
              const uint2* __restrict__ ent, float* __restrict__ out)
{
    extern __shared__ __align__(16) char dsm[];
    uint2 (*sent)[ECH] = (uint2 (*)[ECH])dsm;            // [MG][ECH] = 8KB
    int*   scnt        = (int*)(dsm + MG * ECH * 8);     // [MG]
    float (*buf)[17]   = (float (*)[17])dsm;             // write staging (reuses dsm)

    const int mg = blockIdx.x;            // 0..127
    const int b  = blockIdx.y;            // 0..7
    const int m0 = mg * MG;
    const int tid = threadIdx.x;
    const __half* xtb = xt + (size_t)b * NN * EE;
    float* outb = out + (size_t)b * NN * NN;

    if (tid < MG) scnt[tid] = cnt[b * NN + m0 + tid];
    __syncthreads();
    int maxc = 0;
#pragma unroll
    for (int j = 0; j < MG; j++) maxc = max(maxc, scnt[j]);

    float acc[8][MG];
#pragma unroll
    for (int k = 0; k < 8; k++)
#pragma unroll
        for (int j = 0; j < MG; j++) acc[k][j] = 0.0f;

    const int passes = (maxc + ECH - 1) / ECH;
    for (int pass = 0; pass < passes; pass++) {
        const int srow  = tid >> 4;                      // 0..15
        const int base  = pass * ECH;
        const int avail = min(scnt[srow] - base, ECH);
#pragma unroll
        for (int s2 = 0; s2 < ECH / 16; s2++) {
            const int slot = (tid & 15) + s2 * 16;
            if (slot < avail)
                sent[srow][slot] = ent[(size_t)(b * NN + m0 + srow) * CAP + base + slot];
        }
        __syncthreads();
#pragma unroll
        for (int j = 0; j < MG; j++) {
            const int cj = min(scnt[j] - base, ECH);
            for (int idx = 0; idx < cj; idx++) {
                const uint2 p = sent[j][idx];
                const float w = __uint_as_float(p.y);
                const __half* xr = xtb + (size_t)p.x * NN + tid;
#pragma unroll
                for (int k = 0; k < 8; k++)
                    acc[k][j] = fmaf(w, __half2float(__ldg(xr + k * 256)), acc[k][j]);
            }
        }
        __syncthreads();
    }

    // write: per k, stage [256 n][16 m] in smem, then coalesced float4 stores
#pragma unroll
    for (int k = 0; k < 8; k++) {
        __syncthreads();
#pragma unroll
        for (int j = 0; j < MG; j++) buf[tid][j] = acc[k][j];
        __syncthreads();
#pragma unroll
        for (int s2 = 0; s2 < 4; s2++) {
            const int lin = s2 * 256 + tid;
            const int r   = lin >> 2;
            const int c4  = (lin & 3) * 4;
            const int n   = k * 256 + r;
            *(float4*)(outb + (size_t)n * NN + m0 + c4) =
                make_float4(buf[r][c4], buf[r][c4 + 1], buf[r][c4 + 2], buf[r][c4 + 3]);
        }
    }
}

// ---------------- launch ----------------
extern "C" void kernel_launch(void* const* d_in, const int* in_sizes, int n_in,
                              void* d_out, int out_size)
{
    const float* X = (const float*)d_in[0];
    const float* W = (const float*)d_in[1];
    // d_in[2] = bias: per-column constant on scores -> cancels in axis-1 softmax.
    // d_in[3] = gamma: scalar constant -> cancels likewise. Both unused.
    float* out = (float*)d_out;

    __nv_bfloat16 *xh, *xl, *wh, *wl, *qh, *ql;
    __half *xt;
    float *s, *pm, *ps, *cmax, *csum;
    int *cnt; uint2 *ent;
    cudaGetSymbolAddress((void**)&xh, g_xh);  cudaGetSymbolAddress((void**)&xl, g_xl);
    cudaGetSymbolAddress((void**)&xt, g_xt);
    cudaGetSymbolAddress((void**)&wh, g_wh);  cudaGetSymbolAddress((void**)&wl, g_wl);
    cudaGetSymbolAddress((void**)&qh, g_qh);  cudaGetSymbolAddress((void**)&ql, g_ql);
    cudaGetSymbolAddress((void**)&s,  g_s);
    cudaGetSymbolAddress((void**)&pm, g_pm);  cudaGetSymbolAddress((void**)&ps, g_ps);
    cudaGetSymbolAddress((void**)&cmax, g_cmax);
    cudaGetSymbolAddress((void**)&csum, g_csum);
    cudaGetSymbolAddress((void**)&cnt, g_cnt);
    cudaGetSymbolAddress((void**)&ent, g_ent);

    int dev = 0;  cudaGetDevice(&dev);
    int nsm = 148;
    cudaDeviceGetAttribute(&nsm, cudaDevAttrMultiProcessorCount, dev);

    const int smemG = STAGES * STAGE_BYTES + STAT_BYTES;
    cudaFuncSetAttribute((const void*)gemm_mma<1, false>, cudaFuncAttributeMaxDynamicSharedMemorySize, smemG);
    cudaFuncSetAttribute((const void*)gemm_mma<0, true>,  cudaFuncAttributeMaxDynamicSharedMemorySize, smemG);

    // fused prep: X -> xh/xl/xt (one read), W -> wh/wl
    prep<<<dim3(64, 64, 9), 256>>>(X, W, xh, xl, xt, wh, wl);

    const long long sXE = (long long)NN * EE;
    const long long sNN = (long long)NN * NN;

    // GEMM1: Q = X W^T -> hi/lo bf16. Tiles: gx=16, gy=64.
    gemm_mma<1, false><<<nsm, 256, smemG>>>(xh, xl, wh, wl, 0, 0, 0,
                                            nullptr, qh, ql, 16, 64, 1024,
                                            nullptr, nullptr);

    // GEMM2: S[b] = Q[b] X[b]^T (fp32) + fused per-tile column stats.
    gemm_mma<0, true><<<nsm, 256, smemG>>>(qh, ql, xh, xl, sXE, sXE, sNN,
                                           s, nullptr, nullptr, 16, 8, 1024,
                                           pm, ps);

    // finish column stats; extract sparse attn; sparse output accumulation
    col_finish<<<(BATCH * NN) / 256, 256>>>(pm, ps, cmax, csum);
    extract<<<(BATCH * NN) / 8, 256>>>(s, cmax, csum, cnt, ent);
    {
        const int smemS = 256 * 17 * 4 + 256;   // >= max(entry staging 8KB+64, buf 17408B)
        spmm_out<<<dim3(128, BATCH), 256, smemS>>>(xt, cnt, ent, out);
    }
}

// round 14
// speedup vs baseline: 1.5246x; 1.2798x over previous
#include <cuda_runtime.h>
#include <cuda_bf16.h>
#include <cuda_fp16.h>
#include <cstdint>

#define BATCH 8
#define NN 2048
#define EE 2048

#define BM 256
#define BN 128
#define STAGES 4
#define STAGE_BYTES 49152       // A: 256x128B (32KB) + B: 128x128B (16KB)
#define STAT_BYTES 4096         // 512 x float2 column-stat scratch
#define CAP 2048                // per-row sparse capacity (cannot overflow)
#define ECH 64                  // spmm entry-chunk per pass
#define MG  16                  // spmm m-group

// ---------------- scratch globals (no cudaMalloc allowed) ----------------
__device__ __align__(256) __nv_bfloat16 g_xh[(size_t)BATCH * NN * EE];
__device__ __align__(256) __nv_bfloat16 g_xl[(size_t)BATCH * NN * EE];
__device__ __align__(256) __half        g_xt[(size_t)BATCH * NN * EE];   // X^T per batch [e][n], fp16
__device__ __align__(256) __nv_bfloat16 g_wh[(size_t)EE * EE];
__device__ __align__(256) __nv_bfloat16 g_wl[(size_t)EE * EE];
__device__ __align__(256) float         g_q [(size_t)BATCH * NN * EE];   // exact fp32 Q
__device__ __align__(256) __nv_bfloat16 g_qh[(size_t)BATCH * NN * EE];
__device__ __align__(256) float         g_s [(size_t)BATCH * NN * NN];   // approx scores
__device__ __align__(256) float         g_pm[BATCH * 8 * NN];
__device__ __align__(256) float         g_ps[BATCH * 8 * NN];
__device__ __align__(256) float         g_cmax[BATCH * NN];    // approx cmax, later exact
__device__ __align__(256) float         g_csum[BATCH * NN];    // later exact 1/sum
__device__ __align__(256) unsigned      g_ck[BATCH * NN];      // encoded col max key
__device__ __align__(256) float         g_cs[BATCH * NN];      // col sum accumulator
__device__ __align__(256) int           g_cnt[BATCH * NN];
__device__ __align__(256) uint2         g_ent[(size_t)BATCH * NN * CAP]; // (e, score bits)

// ---------------- helpers ----------------
__device__ __forceinline__ uint32_t smem_u32(const void* p) {
    uint32_t a;
    asm("{ .reg .u64 t; cvta.to.shared.u64 t, %1; cvt.u32.u64 %0, t; }" : "=r"(a) : "l"(p));
    return a;
}
__device__ __forceinline__ void cp16(uint32_t s, const void* g) {
    asm volatile("cp.async.cg.shared.global [%0], [%1], 16;" :: "r"(s), "l"(g) : "memory");
}
__device__ __forceinline__ void cp_commit() {
    asm volatile("cp.async.commit_group;" ::: "memory");
}
template <int N> __device__ __forceinline__ void cp_wait() {
    asm volatile("cp.async.wait_group %0;" :: "n"(N) : "memory");
}
__device__ __forceinline__ void ldm4(uint32_t* r, uint32_t a) {
    asm volatile("ldmatrix.sync.aligned.m8n8.x4.shared.b16 {%0,%1,%2,%3}, [%4];"
                 : "=r"(r[0]), "=r"(r[1]), "=r"(r[2]), "=r"(r[3]) : "r"(a));
}
__device__ __forceinline__ void mma16816(float* c, const uint32_t* a, uint32_t b0, uint32_t b1) {
    asm volatile(
        "mma.sync.aligned.m16n8k16.row.col.f32.bf16.bf16.f32 "
        "{%0,%1,%2,%3}, {%4,%5,%6,%7}, {%8,%9}, {%0,%1,%2,%3};"
        : "+f"(c[0]), "+f"(c[1]), "+f"(c[2]), "+f"(c[3])
        : "r"(a[0]), "r"(a[1]), "r"(a[2]), "r"(a[3]), "r"(b0), "r"(b1));
}
// monotonic float<->uint for atomicMax over signed floats
__device__ __forceinline__ unsigned fenc(float f) {
    unsigned u = __float_as_uint(f);
    return (u & 0x80000000u) ? ~u : (u | 0x80000000u);
}
__device__ __forceinline__ float fdec(unsigned u) {
    u = (u & 0x80000000u) ? (u & 0x7FFFFFFFu) : ~u;
    return __uint_as_float(u);
}

// ---------------- persistent tensor-core GEMM: C tiles 256x128 = A @ B^T ----------------
// NBK=96: 3-phase bf16 split (Ah,Bh)/(Al,Bh)/(Ah,Bl).  NBK=32: 1-phase (Ah,Bh).
// MODE 0: fp32 out (+ fused per-tile column softmax stats when STATS).
// MODE 1: fp32 out AND bf16(out) to outH.
template <int MODE, bool STATS, int NBK>
__global__ __launch_bounds__(256, 1)
void gemm_mma(const void* Ahv, const void* Alv, const void* Bhv, const void* Blv,
              long long aBatch, long long bBatch, long long cBatch,
              float* outF, __nv_bfloat16* outH,
              int gx, int gy, int nTiles, float* pm, float* ps)
{
    extern __shared__ __align__(128) char smem[];
    const uint32_t stg0 = smem_u32(smem);
    const int tid  = threadIdx.x;
    const int lane = tid & 31;
    const int warp = tid >> 5;

    const int lr = tid >> 3;
    const int lc = tid & 7;
    const uint32_t so = (uint32_t)(lr * 128 + ((lc ^ (lr & 7)) << 4));

    const int wm  = warp & 3;
    const int wn  = warp >> 2;
    const int m0w = wm * 64;
    const int n0w = wn * 64;
    const uint32_t aRow  = (uint32_t)(m0w + (lane & 15));
    const uint32_t aBase = aRow * 128;
    const uint32_t aXor  = aRow & 7;
    const uint32_t ac0   = (uint32_t)(lane >> 4);
    const uint32_t bRow  = (uint32_t)(n0w + ((lane >> 4) << 3) + (lane & 7));
    const uint32_t bBase = 32768u + bRow * 128;
    const uint32_t bXor  = (uint32_t)(lane & 7);
    const uint32_t bc0   = (uint32_t)((lane >> 3) & 1);

    float acc[4][8][4] = {};
    uint32_t af[2][4][4], bf[2][4][4];

    const char *gAh, *gAl, *gBh, *gBl;
    auto setLoad = [&](int t) {
        const int bx = t % gx;
        const int r2 = t / gx;
        const int by = r2 % gy;
        const int bz = r2 / gy;
        const size_t aoff = ((size_t)bz * (size_t)aBatch + (size_t)(by * BM + lr) * EE) * 2 + lc * 16;
        const size_t boff = ((size_t)bz * (size_t)bBatch + (size_t)(bx * BN + lr) * EE) * 2 + lc * 16;
        gAh = (const char*)Ahv + aoff;
        gAl = (const char*)Alv + aoff;
        gBh = (const char*)Bhv + boff;
        gBl = (const char*)Blv + boff;
    };

    auto load_chunk = [&](int s, int kbn, int part) {
        const int p = kbn >> 5;
        const char* a = (p == 1) ? gAl : gAh;
        const char* b = (p == 2) ? gBl : gBh;
        const uint32_t koff = (uint32_t)(kbn & 31) * 128;
        const uint32_t dstA = stg0 + (uint32_t)s * STAGE_BYTES + so;
        const uint32_t dstB = dstA + 32768u;
        cp16(dstA + (uint32_t)(part * 2)     * 4096u, a + koff + (size_t)(part * 2)     * 131072);
        cp16(dstA + (uint32_t)(part * 2 + 1) * 4096u, a + koff + (size_t)(part * 2 + 1) * 131072);
        cp16(dstB + (uint32_t)part           * 4096u, b + koff + (size_t)part           * 131072);
        if (part == 3) cp_commit();
    };
    auto ldm_ks = [&](uint32_t sb_, uint32_t ke, int bsel) {
#pragma unroll
        for (int mt = 0; mt < 4; mt++)
            ldm4(af[bsel][mt], sb_ + aBase + mt * 2048u + (((ke * 2 + ac0) ^ aXor) << 4));
#pragma unroll
        for (int np = 0; np < 4; np++)
            ldm4(bf[bsel][np], sb_ + bBase + np * 2048u + (((ke * 2 + bc0) ^ bXor) << 4));
    };

    int t = blockIdx.x;
    if (t >= nTiles) return;
    setLoad(t);
#pragma unroll
    for (int st = 0; st < 3; st++)
        for (int part = 0; part < 4; part++) load_chunk(st, st, part);
    cp_wait<1>();
    __syncthreads();
    ldm_ks(stg0, 0, 0);

    for (;;) {
        const int bx = t % gx;
        const int r2 = t / gx;
        const int row0 = (r2 % gy) * BM;
        const int col0 = bx * BN;
        const int z    = r2 / gy;
        const bool hasNext = (t + (int)gridDim.x) < nTiles;

        for (int kb = 0; kb < NBK; kb++) {
            if (kb == NBK - 3 && hasNext) setLoad(t + (int)gridDim.x);
            const bool doLoad = (kb < NBK - 3) || hasNext;
            const int  kbn    = (kb + 3 < NBK) ? (kb + 3) : (kb + 3 - NBK);
            const uint32_t sb = stg0 + (uint32_t)(kb & 3) * STAGE_BYTES;
#pragma unroll
            for (int ks = 0; ks < 4; ks++) {
                if (doLoad) load_chunk((kb + 3) & 3, kbn, ks);
                const int cur = ks & 1;
                if (ks < 3)
                    ldm_ks(sb, (uint32_t)ks + 1, cur ^ 1);
                else if (kb + 1 < NBK)
                    ldm_ks(stg0 + (uint32_t)((kb + 1) & 3) * STAGE_BYTES, 0, cur ^ 1);
#pragma unroll
                for (int mt = 0; mt < 4; mt++)
#pragma unroll
                    for (int np = 0; np < 4; np++) {
                        mma16816(acc[mt][np * 2],     af[cur][mt], bf[cur][np][0], bf[cur][np][1]);
                        mma16816(acc[mt][np * 2 + 1], af[cur][mt], bf[cur][np][2], bf[cur][np][3]);
                    }
            }
            if (kb + 1 < NBK) {
                if (doLoad) cp_wait<1>(); else cp_wait<0>();
                __syncthreads();
            }
        }
        if (hasNext) cp_wait<1>(); else cp_wait<0>();
        __syncthreads();
        if (hasNext) ldm_ks(stg0, 0, 0);

        // -------- epilogue --------
        const int g  = lane >> 2;
        const int tg = lane & 3;
        float* base = outF + (size_t)z * (size_t)cBatch;
#pragma unroll
        for (int mt = 0; mt < 4; mt++) {
            const int rg = row0 + m0w + mt * 16 + g;
#pragma unroll
            for (int nt = 0; nt < 8; nt++) {
                const int cg = col0 + n0w + nt * 8 + 2 * tg;
                *(float2*)(base + (size_t)rg * 2048 + cg)       = make_float2(acc[mt][nt][0], acc[mt][nt][1]);
                *(float2*)(base + (size_t)(rg + 8) * 2048 + cg) = make_float2(acc[mt][nt][2], acc[mt][nt][3]);
                if (MODE == 1) {
                    *(__nv_bfloat162*)(outH + (size_t)rg * 2048 + cg) =
                        __nv_bfloat162(__float2bfloat16(acc[mt][nt][0]), __float2bfloat16(acc[mt][nt][1]));
                    *(__nv_bfloat162*)(outH + (size_t)(rg + 8) * 2048 + cg) =
                        __nv_bfloat162(__float2bfloat16(acc[mt][nt][2]), __float2bfloat16(acc[mt][nt][3]));
                }
            }
        }
        if (STATS) {
            float2* sst = (float2*)(smem + STAGES * STAGE_BYTES);
#pragma unroll
            for (int nt = 0; nt < 8; nt++) {
#pragma unroll
                for (int p = 0; p < 2; p++) {
                    float m = acc[0][nt][p];
#pragma unroll
                    for (int mt = 0; mt < 4; mt++) {
                        m = fmaxf(m, acc[mt][nt][p]);
                        m = fmaxf(m, acc[mt][nt][2 + p]);
                    }
                    float s = 0.0f;
#pragma unroll
                    for (int mt = 0; mt < 4; mt++) {
                        s += __expf(acc[mt][nt][p]     - m);
                        s += __expf(acc[mt][nt][2 + p] - m);
                    }
#pragma unroll
                    for (int off = 4; off < 32; off <<= 1) {
                        float om = __shfl_xor_sync(0xffffffffu, m, off);
                        float os = __shfl_xor_sync(0xffffffffu, s, off);
                        if (om > m) { s = s * __expf(m - om) + os; m = om; }
                        else        { s += os * __expf(om - m); }
                    }
                    if (lane < 4) {
                        const int colLocal = n0w + nt * 8 + lane * 2 + p;
                        sst[colLocal * 4 + wm] = make_float2(m, s);
                    }
                }
            }
            __syncthreads();
            if (tid < 128) {
                float2 a0 = sst[tid * 4 + 0];
                float2 a1 = sst[tid * 4 + 1];
                float2 a2 = sst[tid * 4 + 2];
                float2 a3 = sst[tid * 4 + 3];
                float M = fmaxf(fmaxf(a0.x, a1.x), fmaxf(a2.x, a3.x));
                float S = a0.y * __expf(a0.x - M) + a1.y * __expf(a1.x - M)
                        + a2.y * __expf(a2.x - M) + a3.y * __expf(a3.x - M);
                const size_t o = ((size_t)z * (size_t)gy + (size_t)(row0 / BM)) * NN
                               + (size_t)(col0 + tid);
                pm[o] = M;
                ps[o] = S;
            }
            __syncthreads();
        }
        if (!hasNext) break;
#pragma unroll
        for (int mt = 0; mt < 4; mt++)
#pragma unroll
            for (int nt = 0; nt < 8; nt++)
#pragma unroll
                for (int q = 0; q < 4; q++) acc[mt][nt][q] = 0.0f;
        t += (int)gridDim.x;
    }
}

// ---------------- fused prep: X -> (bf16 hi/lo + fp16 transpose), W -> bf16 hi/lo ----------------
__global__ __launch_bounds__(256)
void prep(const float* __restrict__ X, const float* __restrict__ W,
          __nv_bfloat16* __restrict__ xh, __nv_bfloat16* __restrict__ xl,
          __half* __restrict__ xt,
          __nv_bfloat16* __restrict__ wh, __nv_bfloat16* __restrict__ wl)
{
    const int c  = threadIdx.x & 31;
    const int r0 = threadIdx.x >> 5;
    const int e0 = blockIdx.x * 32;
    const int n0 = blockIdx.y * 32;
    if (blockIdx.z == 8) {
#pragma unroll
        for (int k = 0; k < 4; k++) {
            const int r = r0 + k * 8;
            const size_t i = (size_t)(n0 + r) * EE + e0 + c;
            const float v = W[i];
            const __nv_bfloat16 h = __float2bfloat16(v);
            wh[i] = h;
            wl[i] = __float2bfloat16(v - __bfloat162float(h));
        }
        return;
    }
    __shared__ float tile[32][33];
    const int b = blockIdx.z;
    const float* Xb  = X  + (size_t)b * NN * EE;
    __half*      xtb = xt + (size_t)b * NN * EE;
#pragma unroll
    for (int k = 0; k < 4; k++) {
        const int r = r0 + k * 8;
        const size_t i = (size_t)(n0 + r) * EE + e0 + c;
        const float v = Xb[i];
        tile[r][c] = v;
        const __nv_bfloat16 h = __float2bfloat16(v);
        xh[(size_t)b * NN * EE + i] = h;
        xl[(size_t)b * NN * EE + i] = __float2bfloat16(v - __bfloat162float(h));
    }
    __syncthreads();
#pragma unroll
    for (int k = 0; k < 4; k++) {
        const int r = r0 + k * 8;
        xtb[(size_t)(e0 + r) * NN + n0 + c] = __float2half(tile[c][r]);
    }
}

// ---------------- combine approx per-tile stats -> approx cmax; init exact accumulators ----
__global__ void col_finish(const float* __restrict__ pm, const float* __restrict__ ps,
                           float* __restrict__ cmax,
                           unsigned* __restrict__ ck, float* __restrict__ cs)
{
    const int i = blockIdx.x * blockDim.x + threadIdx.x;
    const int b = i >> 11, col = i & 2047;
    const float* pmb = pm + (size_t)b * 8 * NN + col;
    float M = pmb[0];
#pragma unroll
    for (int t2 = 1; t2 < 8; t2++) M = fmaxf(M, pmb[(size_t)t2 * NN]);
    cmax[i] = M;
    ck[i] = 0u;      // encoded -inf
    cs[i] = 0.0f;
}

// ---------------- candidate extraction on APPROX scores (threshold -20.5) ----------------
// Approx score error ~0.04 sigma; margin 0.5 -> dropped true weight < ~e^-20: safe.
__global__ __launch_bounds__(256)
void extract(const float* __restrict__ S, const float* __restrict__ cmax,
             int* __restrict__ cnt, uint2* __restrict__ ent)
{
    const int gw   = (int)((blockIdx.x * blockDim.x + threadIdx.x) >> 5);
    const int lane = threadIdx.x & 31;
    const int b = gw >> 11;
    const float* Srow = S + (size_t)gw * NN;
    const float* cmb  = cmax + b * NN;
    uint2* rowEnt = ent + (size_t)gw * CAP;

    int count = 0;
    for (int it = 0; it < 16; it++) {
        const int j0 = it * 128 + lane * 4;
        float4 v  = *(const float4*)(Srow + j0);
        float4 mx = *(const float4*)(cmb  + j0);
        const float vs[4] = {v.x, v.y, v.z, v.w};
        const float ms[4] = {mx.x, mx.y, mx.z, mx.w};
#pragma unroll
        for (int c = 0; c < 4; c++) {
            const bool keep = (vs[c] - ms[c]) > -20.5f;
            const unsigned bal = __ballot_sync(0xffffffffu, keep);
            if (keep) {
                const int pos = count + __popc(bal & ((1u << lane) - 1u));
                rowEnt[pos] = make_uint2((unsigned)(j0 + c), 0u);
            }
            count += __popc(bal);
        }
    }
    if (lane == 0) cnt[gw] = count;
}

// ---------------- exact score recompute for candidates; exact column max ----------------
// Block per attn-row (b,m): Q row cached in smem; warp per candidate dot (fp32).
__global__ __launch_bounds__(128)
void recompute(const float* __restrict__ Q, const float* __restrict__ X,
               const int* __restrict__ cnt, uint2* __restrict__ ent,
               unsigned* __restrict__ ck)
{
    __shared__ float qs[EE];
    const int row  = blockIdx.x;            // b*NN + m
    const int tid  = threadIdx.x;
    const int lane = tid & 31;
    const int w    = tid >> 5;
    const int c    = cnt[row];
    const float4* qrow = (const float4*)(Q + (size_t)row * EE);
#pragma unroll
    for (int i = 0; i < 4; i++) ((float4*)qs)[tid + i * 128] = qrow[tid + i * 128];
    __syncthreads();

    const int b = row >> 11;
    const float* Xb = X + (size_t)b * NN * EE;
    uint2* re = ent + (size_t)row * CAP;
    for (int idx = w; idx < c; idx += 4) {
        const int e = (int)re[idx].x;
        const float4* xr = (const float4*)(Xb + (size_t)e * EE);
        float sum = 0.0f;
#pragma unroll
        for (int i = 0; i < 16; i++) {
            const float4 a  = ((const float4*)qs)[lane + i * 32];
            const float4 x4 = xr[lane + i * 32];
            sum += a.x * x4.x + a.y * x4.y + a.z * x4.z + a.w * x4.w;
        }
#pragma unroll
        for (int off = 16; off; off >>= 1) sum += __shfl_xor_sync(0xffffffffu, sum, off);
        if (lane == 0) {
            re[idx].y = __float_as_uint(sum);
            atomicMax(&ck[b * NN + e], fenc(sum));
        }
    }
}

// ---------------- column denominator over candidates (exact scores) ----------------
__global__ __launch_bounds__(256)
void colsum_pass(const int* __restrict__ cnt, const uint2* __restrict__ ent,
                 const unsigned* __restrict__ ck, float* __restrict__ cs)
{
    const int gw   = blockIdx.x * 8 + (threadIdx.x >> 5);
    const int lane = threadIdx.x & 31;
    const int b = gw >> 11;
    const int c = cnt[gw];
    const uint2* re = ent + (size_t)gw * CAP;
    for (int idx = lane; idx < c; idx += 32) {
        const uint2 p = re[idx];
        const int be = b * NN + (int)p.x;
        atomicAdd(&cs[be], __expf(__uint_as_float(p.y) - fdec(ck[be])));
    }
}

__global__ void finalize_cols(const unsigned* __restrict__ ck, const float* __restrict__ cs,
                              float* __restrict__ cmax, float* __restrict__ crsum)
{
    const int i = blockIdx.x * blockDim.x + threadIdx.x;
    cmax[i]  = fdec(ck[i]);
    crsum[i] = 1.0f / cs[i];
}

// ---------------- sparse output: out[b,n,m] = sum_e w[m,e] * xt[b,e,n] ----------------
__global__ __launch_bounds__(256)
void spmm_out(const __half* __restrict__ xt, const int* __restrict__ cnt,
              const uint2* __restrict__ ent,
              const float* __restrict__ cmax, const float* __restrict__ crsum,
              float* __restrict__ out)
{
    extern __shared__ __align__(16) char dsm[];
    uint2 (*sent)[ECH] = (uint2 (*)[ECH])dsm;            // [MG][ECH] = 8KB
    int*   scnt        = (int*)(dsm + MG * ECH * 8);     // [MG]
    float (*buf)[17]   = (float (*)[17])dsm;             // write staging (reuses dsm)

    const int mg = blockIdx.x;
    const int b  = blockIdx.y;
    const int m0 = mg * MG;
    const int tid = threadIdx.x;
    const __half* xtb = xt + (size_t)b * NN * EE;
    float* outb = out + (size_t)b * NN * NN;

    if (tid < MG) scnt[tid] = cnt[b * NN + m0 + tid];
    __syncthreads();
    int maxc = 0;
#pragma unroll
    for (int j = 0; j < MG; j++) maxc = max(maxc, scnt[j]);

    float acc[8][MG];
#pragma unroll
    for (int k = 0; k < 8; k++)
#pragma unroll
        for (int j = 0; j < MG; j++) acc[k][j] = 0.0f;

    const int passes = (maxc + ECH - 1) / ECH;
    for (int pass = 0; pass < passes; pass++) {
        const int srow  = tid >> 4;
        const int base  = pass * ECH;
        const int avail = min(scnt[srow] - base, ECH);
#pragma unroll
        for (int s2 = 0; s2 < ECH / 16; s2++) {
            const int slot = (tid & 15) + s2 * 16;
            if (slot < avail) {
                uint2 p = ent[(size_t)(b * NN + m0 + srow) * CAP + base + slot];
                const int be = b * NN + (int)p.x;
                const float w = __expf(__uint_as_float(p.y) - __ldg(cmax + be)) * __ldg(crsum + be);
                sent[srow][slot] = make_uint2(p.x, __float_as_uint(w));
            }
        }
        __syncthreads();
#pragma unroll
        for (int j = 0; j < MG; j++) {
            const int cj = min(scnt[j] - base, ECH);
            for (int idx = 0; idx < cj; idx++) {
                const uint2 p = sent[j][idx];
                const float w = __uint_as_float(p.y);
                const __half* xr = xtb + (size_t)p.x * NN + tid;
#pragma unroll
                for (int k = 0; k < 8; k++)
                    acc[k][j] = fmaf(w, __half2float(__ldg(xr + k * 256)), acc[k][j]);
            }
        }
        __syncthreads();
    }

#pragma unroll
    for (int k = 0; k < 8; k++) {
        __syncthreads();
#pragma unroll
        for (int j = 0; j < MG; j++) buf[tid][j] = acc[k][j];
        __syncthreads();
#pragma unroll
        for (int s2 = 0; s2 < 4; s2++) {
            const int lin = s2 * 256 + tid;
            const int r   = lin >> 2;
            const int c4  = (lin & 3) * 4;
            const int n   = k * 256 + r;
            *(float4*)(outb + (size_t)n * NN + m0 + c4) =
                make_float4(buf[r][c4], buf[r][c4 + 1], buf[r][c4 + 2], buf[r][c4 + 3]);
        }
    }
}

// ---------------- launch ----------------
extern "C" void kernel_launch(void* const* d_in, const int* in_sizes, int n_in,
                              void* d_out, int out_size)
{
    const float* X = (const float*)d_in[0];
    const float* W = (const float*)d_in[1];
    // d_in[2] = bias: per-column constant on scores -> cancels in axis-1 softmax.
    // d_in[3] = gamma: scalar constant -> cancels likewise. Both unused.
    float* out = (float*)d_out;

    __nv_bfloat16 *xh, *xl, *wh, *wl, *qh;
    __half *xt;
    float *q, *s, *pm, *ps, *cmax, *csum, *cs;
    unsigned *ck;
    int *cnt; uint2 *ent;
    cudaGetSymbolAddress((void**)&xh, g_xh);  cudaGetSymbolAddress((void**)&xl, g_xl);
    cudaGetSymbolAddress((void**)&xt, g_xt);
    cudaGetSymbolAddress((void**)&wh, g_wh);  cudaGetSymbolAddress((void**)&wl, g_wl);
    cudaGetSymbolAddress((void**)&q,  g_q);   cudaGetSymbolAddress((void**)&qh, g_qh);
    cudaGetSymbolAddress((void**)&s,  g_s);
    cudaGetSymbolAddress((void**)&pm, g_pm);  cudaGetSymbolAddress((void**)&ps, g_ps);
    cudaGetSymbolAddress((void**)&cmax, g_cmax);
    cudaGetSymbolAddress((void**)&csum, g_csum);
    cudaGetSymbolAddress((void**)&ck, g_ck);  cudaGetSymbolAddress((void**)&cs, g_cs);
    cudaGetSymbolAddress((void**)&cnt, g_cnt);
    cudaGetSymbolAddress((void**)&ent, g_ent);

    int dev = 0;  cudaGetDevice(&dev);
    int nsm = 148;
    cudaDeviceGetAttribute(&nsm, cudaDevAttrMultiProcessorCount, dev);

    const int smemG = STAGES * STAGE_BYTES + STAT_BYTES;
    cudaFuncSetAttribute((const void*)gemm_mma<1, false, 96>, cudaFuncAttributeMaxDynamicSharedMemorySize, smemG);
    cudaFuncSetAttribute((const void*)gemm_mma<0, true, 32>,  cudaFuncAttributeMaxDynamicSharedMemorySize, smemG);

    // prep: X -> xh/xl/xt, W -> wh/wl
    prep<<<dim3(64, 64, 9), 256>>>(X, W, xh, xl, xt, wh, wl);

    const long long sXE = (long long)NN * EE;
    const long long sNN = (long long)NN * NN;

    // GEMM1: Q = X W^T. 3-phase bf16 -> exact fp32 Q + bf16 qh.
    gemm_mma<1, false, 96><<<nsm, 256, smemG>>>(xh, xl, wh, wl, 0, 0, 0,
                                                q, qh, 16, 64, 1024,
                                                nullptr, nullptr);

    // GEMM2: approx S[b] = Qh[b] Xh[b]^T. 1-phase bf16 + fused approx stats.
    gemm_mma<0, true, 32><<<nsm, 256, smemG>>>(qh, qh, xh, xh, sXE, sXE, sNN,
                                               s, nullptr, 16, 8, 1024,
                                               pm, ps);

    // approx cmax + init exact accumulators; extract candidates; exact scores;
    // exact denominator; finalize; sparse output.
    col_finish<<<(BATCH * NN) / 256, 256>>>(pm, ps, cmax, ck, cs);
    extract<<<(BATCH * NN) / 8, 256>>>(s, cmax, cnt, ent);
    recompute<<<BATCH * NN, 128>>>(q, X, cnt, ent, ck);
    colsum_pass<<<(BATCH * NN) / 8, 256>>>(cnt, ent, ck, cs);
    finalize_cols<<<(BATCH * NN) / 256, 256>>>(ck, cs, cmax, csum);
    {
        const int smemS = 256 * 17 * 4 + 256;
        spmm_out<<<dim3(128, BATCH), 256, smemS>>>(xt, cnt, ent, cmax, csum, out);
    }
}